// round 4
// baseline (speedup 1.0000x reference)
#include <cuda_runtime.h>

// PairmixLayer: out[n,f,l3^2+c] = sum_{l1,l2} (sum_{a,b} x[n,f,l1^2+a] y[n,f,l2^2+b] cg[l1,l2,l3,a,b,c])
//                                 * (sum_k W[idx(l1,l2,l3)][f][k] g[n,k])
// N=150000, F=64, K=16, L=2.
// Strategy: f32x2 pair-packing over n (FFMA2), dense shared staging for x/y/out,
// cg repacked as padded f32x2 quads for LDS.128, factored contraction
// T_c = sum_a x_a (sum_b y_b cg_abc) to kill the p[5][5] register tile.

#define NF   64
#define KK   16
#define NIDX 27
#define TPB  256
#define PAIRS_PER_BLOCK 4          // 8 n per block
#define ROWSTRIDE 30               // padded u64 slots per (l1,l2,l3,c) row

typedef unsigned long long u64;

// Transposed weights scratch: Wt[idx][k][f]  (coalesced over f for lanes)
__device__ float d_Wt[NIDX * KK * NF];

__device__ __forceinline__ u64 pk2(float lo, float hi) {
    u64 r; asm("mov.b64 %0, {%1,%2};" : "=l"(r) : "f"(lo), "f"(hi)); return r;
}
__device__ __forceinline__ void unpk2(u64 v, float& a, float& b) {
    asm("mov.b64 {%0,%1}, %2;" : "=f"(a), "=f"(b) : "l"(v));
}
__device__ __forceinline__ u64 rep2(float x) {
    u64 r; asm("mov.b64 %0, {%1,%1};" : "=l"(r) : "f"(x)); return r;
}
__device__ __forceinline__ u64 fma2(u64 a, u64 b, u64 c) {
    u64 r; asm("fma.rn.f32x2 %0, %1, %2, %3;" : "=l"(r) : "l"(a), "l"(b), "l"(c)); return r;
}
__device__ __forceinline__ u64 mul2(u64 a, u64 b) {
    u64 r; asm("mul.rn.f32x2 %0, %1, %2;" : "=l"(r) : "l"(a), "l"(b)); return r;
}

// ---------------------------------------------------------------------------
// Kernel 1: transpose weights (27,64,16) -> Wt (27,16,64)
// ---------------------------------------------------------------------------
__global__ void transpose_w_kernel(const float* __restrict__ W) {
    int i = blockIdx.x * blockDim.x + threadIdx.x;
    if (i < NIDX * NF * KK) {
        int idx = i / (NF * KK);
        int rem = i % (NF * KK);
        int f = rem / KK;
        int k = rem % KK;
        d_Wt[(idx * KK + k) * NF + f] = W[i];
    }
}

// ---------------------------------------------------------------------------
// Kernel 2: main. Block = 256 threads = 4 n-pairs x 64 f.
// ---------------------------------------------------------------------------
__global__ __launch_bounds__(TPB)
void pairmix_kernel(const float* __restrict__ x,
                    const float* __restrict__ y,
                    const float* __restrict__ r,
                    const float* __restrict__ cgc,
                    float* __restrict__ out,
                    int N) {
    // cg rows: row = (l1*3+l2)*9 + (l3*l3+c); content [a][b] padded to d2pad=2*l2+2,
    // each element a replicated f32x2 pair -> ulonglong2 (LDS.128) reads 2 b's.
    __shared__ u64 s_cgq[81 * ROWSTRIDE];                       // 19440 B
    __shared__ float s_x[PAIRS_PER_BLOCK * 2 * NF * 9];         // 18432 B
    __shared__ float s_y[PAIRS_PER_BLOCK * 2 * NF * 9];         // 18432 B
    __shared__ float s_o[PAIRS_PER_BLOCK * 2 * NF * 9];         // 18432 B

    const int tid = threadIdx.x;
    const long long nbase = (long long)blockIdx.x * (2 * PAIRS_PER_BLOCK);
    int cnt = N - (int)nbase;                    // rows of n this block owns
    if (cnt > 2 * PAIRS_PER_BLOCK) cnt = 2 * PAIRS_PER_BLOCK;
    const int totf = cnt * NF * 9;               // floats to stage per array

    // ---- stage cg (repacked) ----
    for (int j = tid; j < 81 * ROWSTRIDE; j += TPB) {
        int row = j / ROWSTRIDE, slot = j % ROWSTRIDE;
        int l1l2 = row / 9, cidx = row % 9;
        int l1 = l1l2 / 3, l2 = l1l2 % 3;
        int l3 = (cidx >= 4) ? 2 : (cidx >= 1 ? 1 : 0);
        int c = cidx - l3 * l3;
        int d1 = 2 * l1 + 1, d2 = 2 * l2 + 1, d2pad = d2 + 1;
        int a = slot / d2pad, b = slot % d2pad;
        u64 v = 0ull;
        if (a < d1 && b < d2) {
            int idx = l1 * 9 + l2 * 3 + l3;
            v = rep2(cgc[idx * 125 + a * 25 + b * 5 + c]);
        }
        s_cgq[j] = v;
    }

    // ---- stage x, y dense (contiguous slabs, float4) ----
    {
        const float4* gx = (const float4*)(x + nbase * (NF * 9));
        const float4* gy = (const float4*)(y + nbase * (NF * 9));
        int tot4 = totf >> 2;
        for (int i = tid; i < tot4; i += TPB) {
            ((float4*)s_x)[i] = gx[i];
            ((float4*)s_y)[i] = gy[i];
        }
    }
    __syncthreads();

    // ---- per-thread setup ----
    const int f = tid & 63;
    const int pl = tid >> 6;                 // local pair 0..3
    const int nl0 = pl * 2, nl1 = pl * 2 + 1;
    long long n0 = nbase + nl0;
    long long n1 = nbase + nl1;
    if (n0 > (long long)N - 1) n0 = N - 1;   // clamp (compute garbage, store guarded)
    if (n1 > (long long)N - 1) n1 = N - 1;

    // x/y rows from shared (stride-9 -> conflict-free), pack over pair
    const float* sx0 = s_x + (nl0 * NF + f) * 9;
    const float* sx1 = s_x + (nl1 * NF + f) * 9;
    const float* sy0 = s_y + (nl0 * NF + f) * 9;
    const float* sy1 = s_y + (nl1 * NF + f) * 9;
    u64 xp[9], yp[10];
#pragma unroll
    for (int a = 0; a < 9; a++) {
        xp[a] = pk2(sx0[a], sx1[a]);
        yp[a] = pk2(sy0[a], sy1[a]);
    }
    yp[9] = 0ull;   // pad slot (cg pad is 0 anyway)

    // ---- Bernstein basis, packed over the pair ----
    float r0 = r[n0], r1 = r[n1];
    float u0 = fminf(fmaxf(r0 * 0.2f, 0.0f), 1.0f);
    float u1 = fminf(fmaxf(r1 * 0.2f, 0.0f), 1.0f);
    u64 uu = pk2(u0, u1);
    u64 vv = pk2(1.0f - u0, 1.0f - u1);
    const float binom[KK] = {1.f, 15.f, 105.f, 455.f, 1365.f, 3003.f, 5005.f, 6435.f,
                             6435.f, 5005.f, 3003.f, 1365.f, 455.f, 105.f, 15.f, 1.f};
    u64 gp[KK];
    {
        u64 pu[KK], pv[KK];
        pu[0] = rep2(1.0f);
        pv[0] = rep2(1.0f);
#pragma unroll
        for (int k = 1; k < KK; k++) {
            pu[k] = mul2(pu[k - 1], uu);
            pv[k] = mul2(pv[k - 1], vv);
        }
#pragma unroll
        for (int k = 0; k < KK; k++)
            gp[k] = mul2(mul2(pu[k], pv[(KK - 1) - k]), rep2(binom[k]));
    }

    // ---- main contraction ----
    u64 outp[9];
#pragma unroll
    for (int c = 0; c < 9; c++) outp[c] = 0ull;

#pragma unroll
    for (int l1 = 0; l1 < 3; l1++) {
#pragma unroll
        for (int l2 = 0; l2 < 3; l2++) {
            const int d1 = 2 * l1 + 1;
            const int d2pad = 2 * l2 + 2;
            const int idx0 = l1 * 9 + l2 * 3;
            const int rowbase = (l1 * 3 + l2) * 9;

            // radial mix for the 3 l3's of this (l1,l2)
            u64 ml[3];
#pragma unroll
            for (int l3 = 0; l3 < 3; l3++) {
                const float* w = d_Wt + ((idx0 + l3) * KK) * NF + f;
                u64 acc = 0ull;
#pragma unroll
                for (int k = 0; k < KK; k++)
                    acc = fma2(rep2(w[k * NF]), gp[k], acc);
                ml[l3] = acc;
            }

#pragma unroll
            for (int l3 = 0; l3 < 3; l3++) {
                const int d3 = 2 * l3 + 1;
#pragma unroll
                for (int c = 0; c < d3; c++) {
                    const u64* cgrow = s_cgq + (rowbase + l3 * l3 + c) * ROWSTRIDE;
                    u64 T = 0ull;
#pragma unroll
                    for (int a = 0; a < d1; a++) {
                        u64 q = 0ull;
#pragma unroll
                        for (int bq = 0; bq < d2pad / 2; bq++) {
                            ulonglong2 cgv =
                                *(const ulonglong2*)(cgrow + a * d2pad + 2 * bq);
                            q = fma2(yp[l2 * l2 + 2 * bq], cgv.x, q);
                            q = fma2(yp[l2 * l2 + 2 * bq + 1], cgv.y, q);
                        }
                        T = fma2(xp[l1 * l1 + a], q, T);
                    }
                    outp[l3 * l3 + c] = fma2(T, ml[l3], outp[l3 * l3 + c]);
                }
            }
        }
    }

    // ---- store: stage to shared, then dense float4 STG ----
    float* so0 = s_o + (nl0 * NF + f) * 9;
    float* so1 = s_o + (nl1 * NF + f) * 9;
#pragma unroll
    for (int c = 0; c < 9; c++) {
        float a, b;
        unpk2(outp[c], a, b);
        so0[c] = a;
        so1[c] = b;
    }
    __syncthreads();
    {
        float4* go = (float4*)(out + nbase * (NF * 9));
        int tot4 = totf >> 2;
        for (int i = tid; i < tot4; i += TPB)
            go[i] = ((float4*)s_o)[i];
    }
}

// ---------------------------------------------------------------------------
extern "C" void kernel_launch(void* const* d_in, const int* in_sizes, int n_in,
                              void* d_out, int out_size) {
    const float* x = (const float*)d_in[0];
    const float* y = (const float*)d_in[1];
    const float* r = (const float*)d_in[2];
    const float* weights = (const float*)d_in[3];
    const float* cgc = (const float*)d_in[4];
    float* out = (float*)d_out;

    int N = in_sizes[2];  // r has N elements

    int wtot = NIDX * NF * KK;
    transpose_w_kernel<<<(wtot + 255) / 256, 256>>>(weights);

    int nper = 2 * PAIRS_PER_BLOCK;
    int blocks = (N + nper - 1) / nper;
    pairmix_kernel<<<blocks, TPB>>>(x, y, r, cgc, out, N);
}

// round 5
// speedup vs baseline: 1.0204x; 1.0204x over previous
#include <cuda_runtime.h>

// PairmixLayer: out[n,f,l3^2+c] = sum_{l1,l2} (sum_{a,b} x[n,f,l1^2+a] y[n,f,l2^2+b] cg[l1,l2,l3,a,b,c])
//                                 * (sum_k W[idx(l1,l2,l3)][f][k] g[n,k])
// N=150000, F=64, K=16, L=2.
// R5: f32x2 pair-packing (FFMA2); cg prepacked ONCE into padded f32x2-quad
// layout (LDS.128 reads, linear per-block copy); dense shared staging for
// x/y/out; factored contraction T_c = sum_a x_a (sum_b y_b cg_abc);
// 128-thr CTAs + 47KB smem -> 3 CTAs/SM.

#define NF   64
#define KK   16
#define NIDX 27
#define TPB  128
#define PAIRS_PER_BLOCK 2          // 4 n per block
#define ROWSTRIDE 30               // padded u64 slots per (l1,l2,l3,c) row
#define NROWS 81                   // (l1,l2) x (l3,c) rows
#define NSLAB (PAIRS_PER_BLOCK * 2 * NF * 9)   // 2304 floats

typedef unsigned long long u64;

// Transposed weights: Wt[idx][k][f]  (coalesced over f for lanes)
__device__ float d_Wt[NIDX * KK * NF];
// Prepacked cg: row-major [row][slot], replicated f32x2 pairs, zero-padded
__device__ u64 d_cgq[NROWS * ROWSTRIDE];

__device__ __forceinline__ u64 pk2(float lo, float hi) {
    u64 r; asm("mov.b64 %0, {%1,%2};" : "=l"(r) : "f"(lo), "f"(hi)); return r;
}
__device__ __forceinline__ void unpk2(u64 v, float& a, float& b) {
    asm("mov.b64 {%0,%1}, %2;" : "=f"(a), "=f"(b) : "l"(v));
}
__device__ __forceinline__ u64 rep2(float x) {
    u64 r; asm("mov.b64 %0, {%1,%1};" : "=l"(r) : "f"(x)); return r;
}
__device__ __forceinline__ u64 fma2(u64 a, u64 b, u64 c) {
    u64 r; asm("fma.rn.f32x2 %0, %1, %2, %3;" : "=l"(r) : "l"(a), "l"(b), "l"(c)); return r;
}
__device__ __forceinline__ u64 mul2(u64 a, u64 b) {
    u64 r; asm("mul.rn.f32x2 %0, %1, %2;" : "=l"(r) : "l"(a), "l"(b)); return r;
}

// ---------------------------------------------------------------------------
// Setup kernel 1: transpose weights (27,64,16) -> Wt (27,16,64)
// ---------------------------------------------------------------------------
__global__ void transpose_w_kernel(const float* __restrict__ W) {
    int i = blockIdx.x * blockDim.x + threadIdx.x;
    if (i < NIDX * NF * KK) {
        int idx = i / (NF * KK);
        int rem = i % (NF * KK);
        int f = rem / KK;
        int k = rem % KK;
        d_Wt[(idx * KK + k) * NF + f] = W[i];
    }
}

// ---------------------------------------------------------------------------
// Setup kernel 2: prepack cg into padded f32x2-quad layout (done ONCE).
// row = (l1*3+l2)*9 + (l3*l3+c); slot = a*d2pad + b, d2pad = 2*l2+2.
// ---------------------------------------------------------------------------
__global__ void prepack_cg_kernel(const float* __restrict__ cgc) {
    int j = blockIdx.x * blockDim.x + threadIdx.x;
    if (j >= NROWS * ROWSTRIDE) return;
    int row = j / ROWSTRIDE, slot = j % ROWSTRIDE;
    int l1l2 = row / 9, cidx = row % 9;
    int l1 = l1l2 / 3, l2 = l1l2 % 3;
    int l3 = (cidx >= 4) ? 2 : (cidx >= 1 ? 1 : 0);
    int c = cidx - l3 * l3;
    int d1 = 2 * l1 + 1, d2 = 2 * l2 + 1, d2pad = d2 + 1;
    int a = slot / d2pad, b = slot % d2pad;
    u64 v = 0ull;
    if (a < d1 && b < d2) {
        int idx = l1 * 9 + l2 * 3 + l3;
        v = rep2(cgc[idx * 125 + a * 25 + b * 5 + c]);
    }
    d_cgq[j] = v;
}

// ---------------------------------------------------------------------------
// Main kernel. Block = 128 threads = 2 n-pairs x 64 f.
// ---------------------------------------------------------------------------
__global__ __launch_bounds__(TPB, 3)
void pairmix_kernel(const float* __restrict__ x,
                    const float* __restrict__ y,
                    const float* __restrict__ r,
                    float* __restrict__ out,
                    int N) {
    __shared__ __align__(16) u64 s_cgq[NROWS * ROWSTRIDE];  // 19440 B
    __shared__ __align__(16) float s_x[NSLAB];              //  9216 B
    __shared__ __align__(16) float s_y[NSLAB];              //  9216 B
    __shared__ __align__(16) float s_o[NSLAB];              //  9216 B

    const int tid = threadIdx.x;
    const long long nbase = (long long)blockIdx.x * (2 * PAIRS_PER_BLOCK);
    int cnt = N - (int)nbase;
    if (cnt > 2 * PAIRS_PER_BLOCK) cnt = 2 * PAIRS_PER_BLOCK;
    const int totf = cnt * NF * 9;

    // ---- copy prepacked cg linearly (float4) ----
    {
        const float4* src = (const float4*)d_cgq;
        float4* dst = (float4*)s_cgq;
        const int tot = (NROWS * ROWSTRIDE) >> 1;   // 1215 float4's
#pragma unroll
        for (int i = tid; i < tot; i += TPB) dst[i] = src[i];
    }
    // ---- stage x, y dense (contiguous slabs, float4) ----
    {
        const float4* gx = (const float4*)(x + nbase * (NF * 9));
        const float4* gy = (const float4*)(y + nbase * (NF * 9));
        int tot4 = totf >> 2;
        for (int i = tid; i < tot4; i += TPB) {
            ((float4*)s_x)[i] = gx[i];
            ((float4*)s_y)[i] = gy[i];
        }
    }
    __syncthreads();

    // ---- per-thread setup ----
    const int f = tid & 63;
    const int pl = tid >> 6;                 // local pair 0..PAIRS_PER_BLOCK-1
    const int nl0 = pl * 2, nl1 = pl * 2 + 1;
    long long n0 = nbase + nl0;
    long long n1 = nbase + nl1;
    if (n0 > (long long)N - 1) n0 = N - 1;   // clamp; stores are bounded by totf
    if (n1 > (long long)N - 1) n1 = N - 1;

    const float* sx0 = s_x + (nl0 * NF + f) * 9;
    const float* sx1 = s_x + (nl1 * NF + f) * 9;
    const float* sy0 = s_y + (nl0 * NF + f) * 9;
    const float* sy1 = s_y + (nl1 * NF + f) * 9;
    u64 xp[9], yp[10];
#pragma unroll
    for (int a = 0; a < 9; a++) {
        xp[a] = pk2(sx0[a], sx1[a]);
        yp[a] = pk2(sy0[a], sy1[a]);
    }
    yp[9] = 0ull;   // pad slot (matching cg zero pad)

    // ---- Bernstein basis, packed over the pair ----
    float r0 = r[n0], r1 = r[n1];
    float u0 = fminf(fmaxf(r0 * 0.2f, 0.0f), 1.0f);
    float u1 = fminf(fmaxf(r1 * 0.2f, 0.0f), 1.0f);
    u64 uu = pk2(u0, u1);
    u64 vv = pk2(1.0f - u0, 1.0f - u1);
    const float binom[KK] = {1.f, 15.f, 105.f, 455.f, 1365.f, 3003.f, 5005.f, 6435.f,
                             6435.f, 5005.f, 3003.f, 1365.f, 455.f, 105.f, 15.f, 1.f};
    u64 gp[KK];
    {
        u64 pu[KK], pv[KK];
        pu[0] = rep2(1.0f);
        pv[0] = rep2(1.0f);
#pragma unroll
        for (int k = 1; k < KK; k++) {
            pu[k] = mul2(pu[k - 1], uu);
            pv[k] = mul2(pv[k - 1], vv);
        }
#pragma unroll
        for (int k = 0; k < KK; k++)
            gp[k] = mul2(mul2(pu[k], pv[(KK - 1) - k]), rep2(binom[k]));
    }

    // ---- main contraction ----
    u64 outp[9];
#pragma unroll
    for (int c = 0; c < 9; c++) outp[c] = 0ull;

#pragma unroll
    for (int l1 = 0; l1 < 3; l1++) {
#pragma unroll
        for (int l2 = 0; l2 < 3; l2++) {
            const int d1 = 2 * l1 + 1;
            const int d2pad = 2 * l2 + 2;
            const int idx0 = l1 * 9 + l2 * 3;
            const int rowbase = (l1 * 3 + l2) * 9;

            // radial mix for the 3 l3's of this (l1,l2)
            u64 ml[3];
#pragma unroll
            for (int l3 = 0; l3 < 3; l3++) {
                const float* w = d_Wt + ((idx0 + l3) * KK) * NF + f;
                u64 acc = 0ull;
#pragma unroll
                for (int k = 0; k < KK; k++)
                    acc = fma2(rep2(w[k * NF]), gp[k], acc);
                ml[l3] = acc;
            }

#pragma unroll
            for (int l3 = 0; l3 < 3; l3++) {
                const int d3 = 2 * l3 + 1;
#pragma unroll
                for (int c = 0; c < d3; c++) {
                    const u64* cgrow = s_cgq + (rowbase + l3 * l3 + c) * ROWSTRIDE;
                    u64 T = 0ull;
#pragma unroll
                    for (int a = 0; a < d1; a++) {
                        u64 q = 0ull;
#pragma unroll
                        for (int bq = 0; bq < d2pad / 2; bq++) {
                            ulonglong2 cgv =
                                *(const ulonglong2*)(cgrow + a * d2pad + 2 * bq);
                            q = fma2(yp[l2 * l2 + 2 * bq], cgv.x, q);
                            q = fma2(yp[l2 * l2 + 2 * bq + 1], cgv.y, q);
                        }
                        T = fma2(xp[l1 * l1 + a], q, T);
                    }
                    outp[l3 * l3 + c] = fma2(T, ml[l3], outp[l3 * l3 + c]);
                }
            }
        }
    }

    // ---- store: stage to shared, then dense float4 STG ----
    float* so0 = s_o + (nl0 * NF + f) * 9;
    float* so1 = s_o + (nl1 * NF + f) * 9;
#pragma unroll
    for (int c = 0; c < 9; c++) {
        float a, b;
        unpk2(outp[c], a, b);
        so0[c] = a;
        so1[c] = b;
    }
    __syncthreads();
    {
        float4* go = (float4*)(out + nbase * (NF * 9));
        int tot4 = totf >> 2;
        for (int i = tid; i < tot4; i += TPB)
            go[i] = ((float4*)s_o)[i];
    }
}

// ---------------------------------------------------------------------------
extern "C" void kernel_launch(void* const* d_in, const int* in_sizes, int n_in,
                              void* d_out, int out_size) {
    const float* x = (const float*)d_in[0];
    const float* y = (const float*)d_in[1];
    const float* r = (const float*)d_in[2];
    const float* weights = (const float*)d_in[3];
    const float* cgc = (const float*)d_in[4];
    float* out = (float*)d_out;

    int N = in_sizes[2];  // r has N elements

    int wtot = NIDX * NF * KK;
    transpose_w_kernel<<<(wtot + 255) / 256, 256>>>(weights);
    int ctot = NROWS * ROWSTRIDE;
    prepack_cg_kernel<<<(ctot + 255) / 256, 256>>>(cgc);

    int nper = 2 * PAIRS_PER_BLOCK;
    int blocks = (N + nper - 1) / nper;
    pairmix_kernel<<<blocks, TPB>>>(x, y, r, out, N);
}

// round 6
// speedup vs baseline: 1.5351x; 1.5045x over previous
#include <cuda_runtime.h>

// PairmixLayer: out[n,f,l3^2+c] = sum_{l1,l2} (sum_{a,b} x[n,f,l1^2+a] y[n,f,l2^2+b] cg[l1,l2,l3,a,b,c])
//                                 * (sum_k W[idx(l1,l2,l3)][f][k] g[n,k])
// N=150000, F=64, K=16, L=2.
// R6: R3 memory structure (direct gmem x/y/out, thread=(n-pair,f)) + f32x2
// FFMA2 pair packing + prepacked cg quads (LDS.128 broadcast) + factored
// contraction + split dependency chains + 4 CTAs/SM.

#define NF   64
#define KK   16
#define NIDX 27
#define TPB  128
#define ROWSTRIDE 30               // padded u64 slots per (l1,l2,l3,c) row
#define NROWS 81

typedef unsigned long long u64;

// Transposed weights: Wt[idx][k][f]  (coalesced over f for lanes)
__device__ float d_Wt[NIDX * KK * NF];
// Prepacked cg: [row][slot], replicated f32x2 pairs, zero-padded
__device__ u64 d_cgq[NROWS * ROWSTRIDE];

__device__ __forceinline__ u64 pk2(float lo, float hi) {
    u64 r; asm("mov.b64 %0, {%1,%2};" : "=l"(r) : "f"(lo), "f"(hi)); return r;
}
__device__ __forceinline__ void unpk2(u64 v, float& a, float& b) {
    asm("mov.b64 {%0,%1}, %2;" : "=f"(a), "=f"(b) : "l"(v));
}
__device__ __forceinline__ u64 rep2(float x) {
    u64 r; asm("mov.b64 %0, {%1,%1};" : "=l"(r) : "f"(x)); return r;
}
__device__ __forceinline__ u64 fma2(u64 a, u64 b, u64 c) {
    u64 r; asm("fma.rn.f32x2 %0, %1, %2, %3;" : "=l"(r) : "l"(a), "l"(b), "l"(c)); return r;
}
__device__ __forceinline__ u64 mul2(u64 a, u64 b) {
    u64 r; asm("mul.rn.f32x2 %0, %1, %2;" : "=l"(r) : "l"(a), "l"(b)); return r;
}
__device__ __forceinline__ u64 add2(u64 a, u64 b) {
    u64 r; asm("add.rn.f32x2 %0, %1, %2;" : "=l"(r) : "l"(a), "l"(b)); return r;
}

// ---------------------------------------------------------------------------
// Setup 1: transpose weights (27,64,16) -> Wt (27,16,64)
// ---------------------------------------------------------------------------
__global__ void transpose_w_kernel(const float* __restrict__ W) {
    int i = blockIdx.x * blockDim.x + threadIdx.x;
    if (i < NIDX * NF * KK) {
        int idx = i / (NF * KK);
        int rem = i % (NF * KK);
        int f = rem / KK;
        int k = rem % KK;
        d_Wt[(idx * KK + k) * NF + f] = W[i];
    }
}

// ---------------------------------------------------------------------------
// Setup 2: prepack cg once: row=(l1*3+l2)*9+(l3*l3+c), slot=a*d2pad+b,
// d2pad=2*l2+2, each entry a replicated f32x2 pair, pads zero.
// ---------------------------------------------------------------------------
__global__ void prepack_cg_kernel(const float* __restrict__ cgc) {
    int j = blockIdx.x * blockDim.x + threadIdx.x;
    if (j >= NROWS * ROWSTRIDE) return;
    int row = j / ROWSTRIDE, slot = j % ROWSTRIDE;
    int l1l2 = row / 9, cidx = row % 9;
    int l1 = l1l2 / 3, l2 = l1l2 % 3;
    int l3 = (cidx >= 4) ? 2 : (cidx >= 1 ? 1 : 0);
    int c = cidx - l3 * l3;
    int d1 = 2 * l1 + 1, d2 = 2 * l2 + 1, d2pad = d2 + 1;
    int a = slot / d2pad, b = slot % d2pad;
    u64 v = 0ull;
    if (a < d1 && b < d2) {
        int idx = l1 * 9 + l2 * 3 + l3;
        v = rep2(cgc[idx * 125 + a * 25 + b * 5 + c]);
    }
    d_cgq[j] = v;
}

// ---------------------------------------------------------------------------
// Main kernel. Thread = (n-pair, f). Direct gmem x/y/out. 4 CTAs/SM target.
// ---------------------------------------------------------------------------
__global__ __launch_bounds__(TPB, 4)
void pairmix_kernel(const float* __restrict__ x,
                    const float* __restrict__ y,
                    const float* __restrict__ r,
                    float* __restrict__ out,
                    int N) {
    __shared__ __align__(16) u64 s_cgq[NROWS * ROWSTRIDE];  // 19440 B

    const int tid = threadIdx.x;
    // linear copy of prepacked cg (no per-block repack ALU)
    {
        const float4* src = (const float4*)d_cgq;
        float4* dst = (float4*)s_cgq;
#pragma unroll
        for (int i = tid; i < (NROWS * ROWSTRIDE) >> 1; i += TPB) dst[i] = src[i];
    }
    __syncthreads();

    long long t = (long long)blockIdx.x * TPB + tid;
    int f = (int)(t & 63);
    long long pair = t >> 6;
    long long npairs = ((long long)N + 1) >> 1;
    if (pair >= npairs) return;

    int n0 = (int)(pair * 2);
    int n1 = n0 + 1;
    bool has1 = (n1 < N);
    if (!has1) n1 = n0;

    // ---- direct strided loads of x,y rows, pack over the pair ----
    const float* px0 = x + ((long long)n0 * NF + f) * 9;
    const float* px1 = x + ((long long)n1 * NF + f) * 9;
    const float* py0 = y + ((long long)n0 * NF + f) * 9;
    const float* py1 = y + ((long long)n1 * NF + f) * 9;
    u64 xp[9], yp[10];
#pragma unroll
    for (int a = 0; a < 9; a++) {
        xp[a] = pk2(px0[a], px1[a]);
        yp[a] = pk2(py0[a], py1[a]);
    }
    yp[9] = 0ull;   // pad (cg pad is zero anyway)

    // ---- Bernstein basis, packed over the pair ----
    float r0 = r[n0], r1 = r[n1];
    float u0 = fminf(fmaxf(r0 * 0.2f, 0.0f), 1.0f);
    float u1 = fminf(fmaxf(r1 * 0.2f, 0.0f), 1.0f);
    u64 uu = pk2(u0, u1);
    u64 vv = pk2(1.0f - u0, 1.0f - u1);
    const float binom[KK] = {1.f, 15.f, 105.f, 455.f, 1365.f, 3003.f, 5005.f, 6435.f,
                             6435.f, 5005.f, 3003.f, 1365.f, 455.f, 105.f, 15.f, 1.f};
    u64 gp[KK];
    {
        u64 pu[KK], pv[KK];
        pu[0] = rep2(1.0f);
        pv[0] = rep2(1.0f);
#pragma unroll
        for (int k = 1; k < KK; k++) {
            pu[k] = mul2(pu[k - 1], uu);
            pv[k] = mul2(pv[k - 1], vv);
        }
#pragma unroll
        for (int k = 0; k < KK; k++)
            gp[k] = mul2(mul2(pu[k], pv[(KK - 1) - k]), rep2(binom[k]));
    }

    // ---- main contraction ----
    u64 outp[9];
#pragma unroll
    for (int c = 0; c < 9; c++) outp[c] = 0ull;

#pragma unroll
    for (int l1 = 0; l1 < 3; l1++) {
#pragma unroll
        for (int l2 = 0; l2 < 3; l2++) {
            const int d1 = 2 * l1 + 1;
            const int d2pad = 2 * l2 + 2;
            const int idx0 = l1 * 9 + l2 * 3;
            const int rowbase = (l1 * 3 + l2) * 9;

            // radial mix for the 3 l3's; 16-dot split into two 8-chains
            u64 ml[3];
#pragma unroll
            for (int l3 = 0; l3 < 3; l3++) {
                const float* w = d_Wt + ((idx0 + l3) * KK) * NF + f;
                u64 acc0 = 0ull, acc1 = 0ull;
#pragma unroll
                for (int k = 0; k < KK / 2; k++) {
                    acc0 = fma2(rep2(w[k * NF]), gp[k], acc0);
                    acc1 = fma2(rep2(w[(k + KK / 2) * NF]), gp[k + KK / 2], acc1);
                }
                ml[l3] = add2(acc0, acc1);
            }

#pragma unroll
            for (int l3 = 0; l3 < 3; l3++) {
                const int d3 = 2 * l3 + 1;
#pragma unroll
                for (int c = 0; c < d3; c++) {
                    const u64* cgrow = s_cgq + (rowbase + l3 * l3 + c) * ROWSTRIDE;
                    u64 T0 = 0ull, T1 = 0ull;   // split T chain over a
#pragma unroll
                    for (int a = 0; a < d1; a++) {
                        u64 q = 0ull;
#pragma unroll
                        for (int bq = 0; bq < d2pad / 2; bq++) {
                            ulonglong2 cgv =
                                *(const ulonglong2*)(cgrow + a * d2pad + 2 * bq);
                            q = fma2(yp[l2 * l2 + 2 * bq], cgv.x, q);
                            q = fma2(yp[l2 * l2 + 2 * bq + 1], cgv.y, q);
                        }
                        if (a & 1) T1 = fma2(xp[l1 * l1 + a], q, T1);
                        else       T0 = fma2(xp[l1 * l1 + a], q, T0);
                    }
                    outp[l3 * l3 + c] = fma2(add2(T0, T1), ml[l3], outp[l3 * l3 + c]);
                }
            }
        }
    }

    // ---- direct stores ----
    float* o0 = out + ((long long)n0 * NF + f) * 9;
    float* o1 = out + ((long long)n1 * NF + f) * 9;
#pragma unroll
    for (int c = 0; c < 9; c++) {
        float a, b;
        unpk2(outp[c], a, b);
        o0[c] = a;
        if (has1) o1[c] = b;
    }
}

// ---------------------------------------------------------------------------
extern "C" void kernel_launch(void* const* d_in, const int* in_sizes, int n_in,
                              void* d_out, int out_size) {
    const float* x = (const float*)d_in[0];
    const float* y = (const float*)d_in[1];
    const float* r = (const float*)d_in[2];
    const float* weights = (const float*)d_in[3];
    const float* cgc = (const float*)d_in[4];
    float* out = (float*)d_out;

    int N = in_sizes[2];  // r has N elements

    int wtot = NIDX * NF * KK;
    transpose_w_kernel<<<(wtot + 255) / 256, 256>>>(weights);
    int ctot = NROWS * ROWSTRIDE;
    prepack_cg_kernel<<<(ctot + 255) / 256, 256>>>(cgc);

    long long npairs = ((long long)N + 1) >> 1;
    long long nthreads = npairs * NF;
    int blocks = (int)((nthreads + TPB - 1) / TPB);
    pairmix_kernel<<<blocks, TPB>>>(x, y, r, out, N);
}

// round 8
// speedup vs baseline: 1.9879x; 1.2950x over previous
#include <cuda_runtime.h>

// PairmixLayer: out[n,f,l3^2+c] = sum_{l1,l2} (sum_{a,b} x[n,f,l1^2+a] y[n,f,l2^2+b] cg[l1,l2,l3,a,b,c])
//                                 * (sum_k W[idx(l1,l2,l3)][f][k] g[n,k])
// N=150000, F=64, K=16, L=2.
// R8 = R7 resubmitted after infra failure:
// f32x2 FFMA2 pair packing; cg prepacked as [(l1,l2)][(a,b)][c]-rows of
// replicated f32x2 (5x LDS.128 per (a,b), c innermost); weights as float4
// over k (LDG.128); x/y staged dense through shared; out staged via reused
// x-buffer; 4 CTAs/SM.

#define NF   64
#define KK   16
#define NIDX 27
#define TPB  128
#define PAIRS_PER_BLOCK 2              // 4 n per block
#define NSLAB (PAIRS_PER_BLOCK * 2 * NF * 9)   // 2304 floats
#define CG2TOT 810                     // u64 slots

typedef unsigned long long u64;

// Weights as float4 over k: d_Wt4[(idx*4+kq)*64 + f] = W[idx][f][4kq..4kq+3]
__device__ float4 d_Wt4[NIDX * 4 * NF];
// Prepacked cg: per (l1,l2) block, rows of 10 u64 per (a,b): slot c in 0..8
// holds rep2(cg[l1,l2,l3(c),a,b,c_local]), slot 9 = 0.
__device__ u64 d_cgq2[CG2TOT];

__device__ __forceinline__ u64 pk2(float lo, float hi) {
    u64 r; asm("mov.b64 %0, {%1,%2};" : "=l"(r) : "f"(lo), "f"(hi)); return r;
}
__device__ __forceinline__ void unpk2(u64 v, float& a, float& b) {
    asm("mov.b64 {%0,%1}, %2;" : "=f"(a), "=f"(b) : "l"(v));
}
__device__ __forceinline__ u64 rep2(float x) {
    u64 r; asm("mov.b64 %0, {%1,%1};" : "=l"(r) : "f"(x)); return r;
}
__device__ __forceinline__ u64 fma2(u64 a, u64 b, u64 c) {
    u64 r; asm("fma.rn.f32x2 %0, %1, %2, %3;" : "=l"(r) : "l"(a), "l"(b), "l"(c)); return r;
}
__device__ __forceinline__ u64 mul2(u64 a, u64 b) {
    u64 r; asm("mul.rn.f32x2 %0, %1, %2;" : "=l"(r) : "l"(a), "l"(b)); return r;
}
__device__ __forceinline__ u64 add2(u64 a, u64 b) {
    u64 r; asm("add.rn.f32x2 %0, %1, %2;" : "=l"(r) : "l"(a), "l"(b)); return r;
}

// ---------------------------------------------------------------------------
// Setup 1: weights (27,64,16) -> float4 [idx][kq][f]
// ---------------------------------------------------------------------------
__global__ void prep_w4_kernel(const float* __restrict__ W) {
    int i = blockIdx.x * blockDim.x + threadIdx.x;
    if (i < NIDX * 4 * NF) {
        int idx = i / (4 * NF);
        int rem = i % (4 * NF);
        int kq = rem / NF;
        int f = rem % NF;
        const float* src = W + (idx * NF + f) * KK + 4 * kq;
        d_Wt4[i] = make_float4(src[0], src[1], src[2], src[3]);
    }
}

// ---------------------------------------------------------------------------
// Setup 2: prepack cg. Bases per (l1,l2): size d1*d2*10 u64.
// ---------------------------------------------------------------------------
__global__ void prepack_cg2_kernel(const float* __restrict__ cgc) {
    int j = blockIdx.x * blockDim.x + threadIdx.x;
    if (j >= CG2TOT) return;
    const int bases[10] = {0, 10, 40, 90, 120, 210, 360, 410, 560, 810};
    int g = 0;
    while (j >= bases[g + 1]) g++;
    int l1 = g / 3, l2 = g % 3;
    int off = j - bases[g];
    int ab = off / 10, c = off % 10;
    int d2 = 2 * l2 + 1;
    int a = ab / d2, b = ab % d2;
    u64 v = 0ull;
    if (c < 9) {
        int l3 = (c >= 4) ? 2 : (c >= 1 ? 1 : 0);
        int cl = c - l3 * l3;
        int idx = l1 * 9 + l2 * 3 + l3;
        v = rep2(cgc[idx * 125 + a * 25 + b * 5 + cl]);
    }
    d_cgq2[j] = v;
}

// ---------------------------------------------------------------------------
// Main kernel. Block = 128 threads = 2 n-pairs x 64 f.
// ---------------------------------------------------------------------------
__global__ __launch_bounds__(TPB, 4)
void pairmix_kernel(const float* __restrict__ x,
                    const float* __restrict__ y,
                    const float* __restrict__ r,
                    float* __restrict__ out,
                    int N) {
    __shared__ __align__(16) u64 s_cg[CG2TOT];     // 6480 B
    __shared__ __align__(16) float s_x[NSLAB];     // 9216 B (reused for out)
    __shared__ __align__(16) float s_y[NSLAB];     // 9216 B

    const int tid = threadIdx.x;
    const long long nbase = (long long)blockIdx.x * (2 * PAIRS_PER_BLOCK);
    int cnt = N - (int)nbase;
    if (cnt > 2 * PAIRS_PER_BLOCK) cnt = 2 * PAIRS_PER_BLOCK;
    const int totf = cnt * NF * 9;

    // copy prepacked cg linearly (float4)
    {
        const float4* src = (const float4*)d_cgq2;
        float4* dst = (float4*)s_cg;
#pragma unroll
        for (int i = tid; i < CG2TOT >> 1; i += TPB) dst[i] = src[i];
    }
    // stage x, y dense (contiguous slabs, float4)
    {
        const float4* gx = (const float4*)(x + nbase * (NF * 9));
        const float4* gy = (const float4*)(y + nbase * (NF * 9));
        int tot4 = totf >> 2;
        for (int i = tid; i < tot4; i += TPB) {
            ((float4*)s_x)[i] = gx[i];
            ((float4*)s_y)[i] = gy[i];
        }
    }
    __syncthreads();

    const int f = tid & 63;
    const int pl = tid >> 6;
    const int nl0 = pl * 2, nl1 = pl * 2 + 1;
    long long n0 = nbase + nl0;
    long long n1 = nbase + nl1;
    if (n0 > (long long)N - 1) n0 = N - 1;
    if (n1 > (long long)N - 1) n1 = N - 1;

    // x/y rows from shared (stride-9, conflict-free), packed over pair
    const float* sx0 = s_x + (nl0 * NF + f) * 9;
    const float* sx1 = s_x + (nl1 * NF + f) * 9;
    const float* sy0 = s_y + (nl0 * NF + f) * 9;
    const float* sy1 = s_y + (nl1 * NF + f) * 9;
    u64 xp[9], yp[9];
#pragma unroll
    for (int a = 0; a < 9; a++) {
        xp[a] = pk2(sx0[a], sx1[a]);
        yp[a] = pk2(sy0[a], sy1[a]);
    }

    // Bernstein basis, packed over the pair
    float r0 = r[n0], r1 = r[n1];
    float u0 = fminf(fmaxf(r0 * 0.2f, 0.0f), 1.0f);
    float u1 = fminf(fmaxf(r1 * 0.2f, 0.0f), 1.0f);
    u64 uu = pk2(u0, u1);
    u64 vv = pk2(1.0f - u0, 1.0f - u1);
    const float binom[KK] = {1.f, 15.f, 105.f, 455.f, 1365.f, 3003.f, 5005.f, 6435.f,
                             6435.f, 5005.f, 3003.f, 1365.f, 455.f, 105.f, 15.f, 1.f};
    u64 gp[KK];
    {
        u64 pu[KK], pv[KK];
        pu[0] = rep2(1.0f);
        pv[0] = rep2(1.0f);
#pragma unroll
        for (int k = 1; k < KK; k++) {
            pu[k] = mul2(pu[k - 1], uu);
            pv[k] = mul2(pv[k - 1], vv);
        }
#pragma unroll
        for (int k = 0; k < KK; k++)
            gp[k] = mul2(mul2(pu[k], pv[(KK - 1) - k]), rep2(binom[k]));
    }

    // main contraction
    const int bases[9] = {0, 10, 40, 90, 120, 210, 360, 410, 560};
    u64 outp[9];
#pragma unroll
    for (int c = 0; c < 9; c++) outp[c] = 0ull;

#pragma unroll
    for (int l1 = 0; l1 < 3; l1++) {
#pragma unroll
        for (int l2 = 0; l2 < 3; l2++) {
            const int d1 = 2 * l1 + 1;
            const int d2 = 2 * l2 + 1;
            const int idx0 = l1 * 9 + l2 * 3;
            const u64* cgblk = s_cg + bases[l1 * 3 + l2];

            // radial mix for the 3 l3's (float4 weight loads, split chains)
            u64 ml[3];
#pragma unroll
            for (int l3 = 0; l3 < 3; l3++) {
                const float4* w = d_Wt4 + ((idx0 + l3) * 4) * NF + f;
                u64 a0 = 0ull, a1 = 0ull;
#pragma unroll
                for (int kq = 0; kq < 4; kq++) {
                    float4 wv = w[kq * NF];
                    a0 = fma2(rep2(wv.x), gp[4 * kq + 0], a0);
                    a1 = fma2(rep2(wv.y), gp[4 * kq + 1], a1);
                    a0 = fma2(rep2(wv.z), gp[4 * kq + 2], a0);
                    a1 = fma2(rep2(wv.w), gp[4 * kq + 3], a1);
                }
                ml[l3] = add2(a0, a1);
            }

            // U_c = sum_ab x_a y_b cg[abc]  (c innermost, 10 independent chains)
            u64 U[10];
#pragma unroll
            for (int c = 0; c < 10; c++) U[c] = 0ull;
#pragma unroll
            for (int a = 0; a < d1; a++) {
                const u64 xa = xp[l1 * l1 + a];
#pragma unroll
                for (int b = 0; b < d2; b++) {
                    const u64 p = mul2(xa, yp[l2 * l2 + b]);
                    const u64* row = cgblk + (a * d2 + b) * 10;
#pragma unroll
                    for (int cq = 0; cq < 5; cq++) {
                        ulonglong2 v = *(const ulonglong2*)(row + 2 * cq);
                        U[2 * cq]     = fma2(p, v.x, U[2 * cq]);
                        U[2 * cq + 1] = fma2(p, v.y, U[2 * cq + 1]);
                    }
                }
            }
            // epilogue: out_c += U_c * ml[l3(c)]
            outp[0] = fma2(U[0], ml[0], outp[0]);
#pragma unroll
            for (int c = 1; c < 4; c++) outp[c] = fma2(U[c], ml[1], outp[c]);
#pragma unroll
            for (int c = 4; c < 9; c++) outp[c] = fma2(U[c], ml[2], outp[c]);
        }
    }

    // store: stage into reused s_x, then dense float4 STG
    __syncthreads();
    {
        float* so0 = s_x + (nl0 * NF + f) * 9;
        float* so1 = s_x + (nl1 * NF + f) * 9;
#pragma unroll
        for (int c = 0; c < 9; c++) {
            float a, b;
            unpk2(outp[c], a, b);
            so0[c] = a;
            so1[c] = b;
        }
    }
    __syncthreads();
    {
        float4* go = (float4*)(out + nbase * (NF * 9));
        int tot4 = totf >> 2;
        for (int i = tid; i < tot4; i += TPB)
            go[i] = ((float4*)s_x)[i];
    }
}

// ---------------------------------------------------------------------------
extern "C" void kernel_launch(void* const* d_in, const int* in_sizes, int n_in,
                              void* d_out, int out_size) {
    const float* x = (const float*)d_in[0];
    const float* y = (const float*)d_in[1];
    const float* r = (const float*)d_in[2];
    const float* weights = (const float*)d_in[3];
    const float* cgc = (const float*)d_in[4];
    float* out = (float*)d_out;

    int N = in_sizes[2];  // r has N elements

    int wtot = NIDX * 4 * NF;
    prep_w4_kernel<<<(wtot + 255) / 256, 256>>>(weights);
    prepack_cg2_kernel<<<(CG2TOT + 255) / 256, 256>>>(cgc);

    int nper = 2 * PAIRS_PER_BLOCK;
    int blocks = (N + nper - 1) / nper;
    pairmix_kernel<<<blocks, TPB>>>(x, y, r, out, N);
}

// round 11
// speedup vs baseline: 2.0499x; 1.0312x over previous
#include <cuda_runtime.h>

// PairmixLayer: out[n,f,l3^2+c] = sum_{l1,l2} (sum_{a,b} x[n,f,l1^2+a] y[n,f,l2^2+b] cg[l1,l2,l3,a,b,c])
//                                 * (sum_k W[idx(l1,l2,l3)][f][k] g[n,k])
// N=150000, F=64, K=16, L=2.
// R10 = R9 resubmitted after infra failure:
// R8 + warp remap (warp = 16 f x 2 pairs -> weight LDG sector dedup,
// halving weight wavefronts) + 8-float per-n skew on staged slabs to keep
// LDS conflict-free under the new lane layout.

#define NF   64
#define KK   16
#define NIDX 27
#define TPB  128
#define PAIRS_PER_BLOCK 2              // 4 n per block
#define SKEW 8                         // floats of per-n slab skew
#define NPB  (PAIRS_PER_BLOCK * 2)     // 4 n per block
#define SLABF (NF * 9)                 // 576 floats per n
#define SLABP (SLABF + SKEW)           // 584 floats per n (padded)
#define CG2TOT 810                     // u64 slots

typedef unsigned long long u64;

// Weights as float4 over k: d_Wt4[(idx*4+kq)*64 + f] = W[idx][f][4kq..4kq+3]
__device__ float4 d_Wt4[NIDX * 4 * NF];
// Prepacked cg: per (l1,l2) block, rows of 10 u64 per (a,b): slot c in 0..8
// holds rep2(cg[l1,l2,l3(c),a,b,c_local]), slot 9 = 0.
__device__ u64 d_cgq2[CG2TOT];

__device__ __forceinline__ u64 pk2(float lo, float hi) {
    u64 r; asm("mov.b64 %0, {%1,%2};" : "=l"(r) : "f"(lo), "f"(hi)); return r;
}
__device__ __forceinline__ void unpk2(u64 v, float& a, float& b) {
    asm("mov.b64 {%0,%1}, %2;" : "=f"(a), "=f"(b) : "l"(v));
}
__device__ __forceinline__ u64 rep2(float x) {
    u64 r; asm("mov.b64 %0, {%1,%1};" : "=l"(r) : "f"(x)); return r;
}
__device__ __forceinline__ u64 fma2(u64 a, u64 b, u64 c) {
    u64 r; asm("fma.rn.f32x2 %0, %1, %2, %3;" : "=l"(r) : "l"(a), "l"(b), "l"(c)); return r;
}
__device__ __forceinline__ u64 mul2(u64 a, u64 b) {
    u64 r; asm("mul.rn.f32x2 %0, %1, %2;" : "=l"(r) : "l"(a), "l"(b)); return r;
}
__device__ __forceinline__ u64 add2(u64 a, u64 b) {
    u64 r; asm("add.rn.f32x2 %0, %1, %2;" : "=l"(r) : "l"(a), "l"(b)); return r;
}

// ---------------------------------------------------------------------------
// Setup 1: weights (27,64,16) -> float4 [idx][kq][f]
// ---------------------------------------------------------------------------
__global__ void prep_w4_kernel(const float* __restrict__ W) {
    int i = blockIdx.x * blockDim.x + threadIdx.x;
    if (i < NIDX * 4 * NF) {
        int idx = i / (4 * NF);
        int rem = i % (4 * NF);
        int kq = rem / NF;
        int f = rem % NF;
        const float* src = W + (idx * NF + f) * KK + 4 * kq;
        d_Wt4[i] = make_float4(src[0], src[1], src[2], src[3]);
    }
}

// ---------------------------------------------------------------------------
// Setup 2: prepack cg. Bases per (l1,l2): size d1*d2*10 u64.
// ---------------------------------------------------------------------------
__global__ void prepack_cg2_kernel(const float* __restrict__ cgc) {
    int j = blockIdx.x * blockDim.x + threadIdx.x;
    if (j >= CG2TOT) return;
    const int bases[10] = {0, 10, 40, 90, 120, 210, 360, 410, 560, 810};
    int g = 0;
    while (j >= bases[g + 1]) g++;
    int l1 = g / 3, l2 = g % 3;
    int off = j - bases[g];
    int ab = off / 10, c = off % 10;
    int d2 = 2 * l2 + 1;
    int a = ab / d2, b = ab % d2;
    u64 v = 0ull;
    if (c < 9) {
        int l3 = (c >= 4) ? 2 : (c >= 1 ? 1 : 0);
        int cl = c - l3 * l3;
        int idx = l1 * 9 + l2 * 3 + l3;
        v = rep2(cgc[idx * 125 + a * 25 + b * 5 + cl]);
    }
    d_cgq2[j] = v;
}

// ---------------------------------------------------------------------------
// Main kernel. Block = 128 threads = 4 n x 64 f, warp = 16 f x 2 pairs.
// ---------------------------------------------------------------------------
__global__ __launch_bounds__(TPB, 4)
void pairmix_kernel(const float* __restrict__ x,
                    const float* __restrict__ y,
                    const float* __restrict__ r,
                    float* __restrict__ out,
                    int N) {
    __shared__ __align__(16) u64 s_cg[CG2TOT];          //  6480 B
    __shared__ __align__(16) float s_x[NPB * SLABP];    //  9344 B (reused for out)
    __shared__ __align__(16) float s_y[NPB * SLABP];    //  9344 B

    const int tid = threadIdx.x;
    const long long nbase = (long long)blockIdx.x * NPB;
    int cnt = N - (int)nbase;
    if (cnt > NPB) cnt = NPB;
    const int totf = cnt * SLABF;

    // copy prepacked cg linearly (float4)
    {
        const float4* src = (const float4*)d_cgq2;
        float4* dst = (float4*)s_cg;
#pragma unroll
        for (int i = tid; i < CG2TOT >> 1; i += TPB) dst[i] = src[i];
    }
    // stage x, y dense (contiguous slabs, float4), skewed by SKEW floats per n
    {
        const float4* gx = (const float4*)(x + nbase * SLABF);
        const float4* gy = (const float4*)(y + nbase * SLABF);
        int tot4 = totf >> 2;                 // 144 float4 per n
        for (int i = tid; i < tot4; i += TPB) {
            int di = i + (i / 144) * (SKEW / 4);
            ((float4*)s_x)[di] = gx[i];
            ((float4*)s_y)[di] = gy[i];
        }
    }
    __syncthreads();

    // warp = 16 f x 2 pairs: lanes 0-15 pair0, lanes 16-31 pair1 (same f set)
    const int lane = tid & 31;
    const int wid = tid >> 5;
    const int pl = lane >> 4;                 // pair 0/1
    const int f = (wid << 4) | (lane & 15);   // 0..63
    const int nl0 = pl * 2, nl1 = pl * 2 + 1;
    long long n0 = nbase + nl0;
    long long n1 = nbase + nl1;
    if (n0 > (long long)N - 1) n0 = N - 1;
    if (n1 > (long long)N - 1) n1 = N - 1;

    // x/y rows from shared (skewed slabs -> conflict-free), packed over pair
    const float* sx0 = s_x + nl0 * SLABP + f * 9;
    const float* sx1 = s_x + nl1 * SLABP + f * 9;
    const float* sy0 = s_y + nl0 * SLABP + f * 9;
    const float* sy1 = s_y + nl1 * SLABP + f * 9;
    u64 xp[9], yp[9];
#pragma unroll
    for (int a = 0; a < 9; a++) {
        xp[a] = pk2(sx0[a], sx1[a]);
        yp[a] = pk2(sy0[a], sy1[a]);
    }

    // Bernstein basis, packed over the pair
    float r0 = r[n0], r1 = r[n1];
    float u0 = fminf(fmaxf(r0 * 0.2f, 0.0f), 1.0f);
    float u1 = fminf(fmaxf(r1 * 0.2f, 0.0f), 1.0f);
    u64 uu = pk2(u0, u1);
    u64 vv = pk2(1.0f - u0, 1.0f - u1);
    const float binom[KK] = {1.f, 15.f, 105.f, 455.f, 1365.f, 3003.f, 5005.f, 6435.f,
                             6435.f, 5005.f, 3003.f, 1365.f, 455.f, 105.f, 15.f, 1.f};
    u64 gp[KK];
    {
        u64 pu[KK], pv[KK];
        pu[0] = rep2(1.0f);
        pv[0] = rep2(1.0f);
#pragma unroll
        for (int k = 1; k < KK; k++) {
            pu[k] = mul2(pu[k - 1], uu);
            pv[k] = mul2(pv[k - 1], vv);
        }
#pragma unroll
        for (int k = 0; k < KK; k++)
            gp[k] = mul2(mul2(pu[k], pv[(KK - 1) - k]), rep2(binom[k]));
    }

    // main contraction
    const int bases[9] = {0, 10, 40, 90, 120, 210, 360, 410, 560};
    u64 outp[9];
#pragma unroll
    for (int c = 0; c < 9; c++) outp[c] = 0ull;

#pragma unroll
    for (int l1 = 0; l1 < 3; l1++) {
#pragma unroll
        for (int l2 = 0; l2 < 3; l2++) {
            const int d1 = 2 * l1 + 1;
            const int d2 = 2 * l2 + 1;
            const int idx0 = l1 * 9 + l2 * 3;
            const u64* cgblk = s_cg + bases[l1 * 3 + l2];

            // radial mix for the 3 l3's (float4 weight loads, lane-deduped)
            u64 ml[3];
#pragma unroll
            for (int l3 = 0; l3 < 3; l3++) {
                const float4* w = d_Wt4 + ((idx0 + l3) * 4) * NF + f;
                u64 a0 = 0ull, a1 = 0ull;
#pragma unroll
                for (int kq = 0; kq < 4; kq++) {
                    float4 wv = w[kq * NF];
                    a0 = fma2(rep2(wv.x), gp[4 * kq + 0], a0);
                    a1 = fma2(rep2(wv.y), gp[4 * kq + 1], a1);
                    a0 = fma2(rep2(wv.z), gp[4 * kq + 2], a0);
                    a1 = fma2(rep2(wv.w), gp[4 * kq + 3], a1);
                }
                ml[l3] = add2(a0, a1);
            }

            // U_c = sum_ab x_a y_b cg[abc]  (c innermost, 10 independent chains)
            u64 U[10];
#pragma unroll
            for (int c = 0; c < 10; c++) U[c] = 0ull;
#pragma unroll
            for (int a = 0; a < d1; a++) {
                const u64 xa = xp[l1 * l1 + a];
#pragma unroll
                for (int b = 0; b < d2; b++) {
                    const u64 p = mul2(xa, yp[l2 * l2 + b]);
                    const u64* row = cgblk + (a * d2 + b) * 10;
#pragma unroll
                    for (int cq = 0; cq < 5; cq++) {
                        ulonglong2 v = *(const ulonglong2*)(row + 2 * cq);
                        U[2 * cq]     = fma2(p, v.x, U[2 * cq]);
                        U[2 * cq + 1] = fma2(p, v.y, U[2 * cq + 1]);
                    }
                }
            }
            // epilogue: out_c += U_c * ml[l3(c)]
            outp[0] = fma2(U[0], ml[0], outp[0]);
#pragma unroll
            for (int c = 1; c < 4; c++) outp[c] = fma2(U[c], ml[1], outp[c]);
#pragma unroll
            for (int c = 4; c < 9; c++) outp[c] = fma2(U[c], ml[2], outp[c]);
        }
    }

    // store: stage into reused s_x (skewed), then dense float4 STG
    __syncthreads();
    {
        float* so0 = s_x + nl0 * SLABP + f * 9;
        float* so1 = s_x + nl1 * SLABP + f * 9;
#pragma unroll
        for (int c = 0; c < 9; c++) {
            float a, b;
            unpk2(outp[c], a, b);
            so0[c] = a;
            so1[c] = b;
        }
    }
    __syncthreads();
    {
        float4* go = (float4*)(out + nbase * SLABF);
        int tot4 = totf >> 2;
        for (int i = tid; i < tot4; i += TPB) {
            int si = i + (i / 144) * (SKEW / 4);
            go[i] = ((float4*)s_x)[si];
        }
    }
}

// ---------------------------------------------------------------------------
extern "C" void kernel_launch(void* const* d_in, const int* in_sizes, int n_in,
                              void* d_out, int out_size) {
    const float* x = (const float*)d_in[0];
    const float* y = (const float*)d_in[1];
    const float* r = (const float*)d_in[2];
    const float* weights = (const float*)d_in[3];
    const float* cgc = (const float*)d_in[4];
    float* out = (float*)d_out;

    int N = in_sizes[2];  // r has N elements

    int wtot = NIDX * 4 * NF;
    prep_w4_kernel<<<(wtot + 255) / 256, 256>>>(weights);
    prepack_cg2_kernel<<<(CG2TOT + 255) / 256, 256>>>(cgc);

    int blocks = (N + NPB - 1) / NPB;
    pairmix_kernel<<<blocks, TPB>>>(x, y, r, out, N);
}

// round 14
// speedup vs baseline: 2.0586x; 1.0042x over previous
#include <cuda_runtime.h>

// PairmixLayer: out[n,f,l3^2+c] = sum_{l1,l2} (sum_{a,b} x[n,f,l1^2+a] y[n,f,l2^2+b] cg[l1,l2,l3,a,b,c])
//                                 * (sum_k W[idx(l1,l2,l3)][f][k] g[n,k])
// N=150000, F=64, K=16, L=2.
// R12 = R11 + merged single setup kernel (2 launches/call -> ncu alignment
// lands on pairmix) + removal of the dead pad chain U[9] (4xLDS.128+1xLDS.64,
// 9 FMA2 per (a,b) row).

#define NF   64
#define KK   16
#define NIDX 27
#define TPB  128
#define PAIRS_PER_BLOCK 2              // 4 n per block
#define SKEW 8                         // floats of per-n slab skew
#define NPB  (PAIRS_PER_BLOCK * 2)     // 4 n per block
#define SLABF (NF * 9)                 // 576 floats per n
#define SLABP (SLABF + SKEW)           // 584 floats per n (padded)
#define CG2TOT 810                     // u64 slots
#define WTOT  (NIDX * 4 * NF)          // 6912 float4 elems

typedef unsigned long long u64;

// Weights as float4 over k: d_Wt4[(idx*4+kq)*64 + f] = W[idx][f][4kq..4kq+3]
__device__ float4 d_Wt4[WTOT];
// Prepacked cg: per (l1,l2) block, rows of 10 u64 per (a,b): slot c in 0..8
// holds rep2(cg[l1,l2,l3(c),a,b,c_local]), slot 9 = 0.
__device__ u64 d_cgq2[CG2TOT];

__device__ __forceinline__ u64 pk2(float lo, float hi) {
    u64 r; asm("mov.b64 %0, {%1,%2};" : "=l"(r) : "f"(lo), "f"(hi)); return r;
}
__device__ __forceinline__ void unpk2(u64 v, float& a, float& b) {
    asm("mov.b64 {%0,%1}, %2;" : "=f"(a), "=f"(b) : "l"(v));
}
__device__ __forceinline__ u64 rep2(float x) {
    u64 r; asm("mov.b64 %0, {%1,%1};" : "=l"(r) : "f"(x)); return r;
}
__device__ __forceinline__ u64 fma2(u64 a, u64 b, u64 c) {
    u64 r; asm("fma.rn.f32x2 %0, %1, %2, %3;" : "=l"(r) : "l"(a), "l"(b), "l"(c)); return r;
}
__device__ __forceinline__ u64 mul2(u64 a, u64 b) {
    u64 r; asm("mul.rn.f32x2 %0, %1, %2;" : "=l"(r) : "l"(a), "l"(b)); return r;
}
__device__ __forceinline__ u64 add2(u64 a, u64 b) {
    u64 r; asm("add.rn.f32x2 %0, %1, %2;" : "=l"(r) : "l"(a), "l"(b)); return r;
}

// ---------------------------------------------------------------------------
// Merged setup kernel: weights repack + cg prepack in one launch.
// ---------------------------------------------------------------------------
__global__ void setup_kernel(const float* __restrict__ W,
                             const float* __restrict__ cgc) {
    int i = blockIdx.x * blockDim.x + threadIdx.x;
    if (i < WTOT) {
        int idx = i / (4 * NF);
        int rem = i % (4 * NF);
        int kq = rem / NF;
        int f = rem % NF;
        const float* src = W + (idx * NF + f) * KK + 4 * kq;
        d_Wt4[i] = make_float4(src[0], src[1], src[2], src[3]);
    } else {
        int j = i - WTOT;
        if (j < CG2TOT) {
            const int bases[10] = {0, 10, 40, 90, 120, 210, 360, 410, 560, 810};
            int g = 0;
            while (j >= bases[g + 1]) g++;
            int l1 = g / 3, l2 = g % 3;
            int off = j - bases[g];
            int ab = off / 10, c = off % 10;
            int d2 = 2 * l2 + 1;
            int a = ab / d2, b = ab % d2;
            u64 v = 0ull;
            if (c < 9) {
                int l3 = (c >= 4) ? 2 : (c >= 1 ? 1 : 0);
                int cl = c - l3 * l3;
                int idx = l1 * 9 + l2 * 3 + l3;
                v = rep2(cgc[idx * 125 + a * 25 + b * 5 + cl]);
            }
            d_cgq2[j] = v;
        }
    }
}

// ---------------------------------------------------------------------------
// Main kernel. Block = 128 threads = 4 n x 64 f, warp = 16 f x 2 pairs.
// ---------------------------------------------------------------------------
__global__ __launch_bounds__(TPB, 4)
void pairmix_kernel(const float* __restrict__ x,
                    const float* __restrict__ y,
                    const float* __restrict__ r,
                    float* __restrict__ out,
                    int N) {
    __shared__ __align__(16) u64 s_cg[CG2TOT];          //  6480 B
    __shared__ __align__(16) float s_x[NPB * SLABP];    //  9344 B (reused for out)
    __shared__ __align__(16) float s_y[NPB * SLABP];    //  9344 B

    const int tid = threadIdx.x;
    const long long nbase = (long long)blockIdx.x * NPB;
    int cnt = N - (int)nbase;
    if (cnt > NPB) cnt = NPB;
    const int totf = cnt * SLABF;

    // copy prepacked cg linearly (float4)
    {
        const float4* src = (const float4*)d_cgq2;
        float4* dst = (float4*)s_cg;
#pragma unroll
        for (int i = tid; i < CG2TOT >> 1; i += TPB) dst[i] = src[i];
    }
    // stage x, y dense (contiguous slabs, float4), skewed by SKEW floats per n
    {
        const float4* gx = (const float4*)(x + nbase * SLABF);
        const float4* gy = (const float4*)(y + nbase * SLABF);
        int tot4 = totf >> 2;                 // 144 float4 per n
        for (int i = tid; i < tot4; i += TPB) {
            int di = i + (i / 144) * (SKEW / 4);
            ((float4*)s_x)[di] = gx[i];
            ((float4*)s_y)[di] = gy[i];
        }
    }
    __syncthreads();

    // warp = 16 f x 2 pairs: lanes 0-15 pair0, lanes 16-31 pair1 (same f set)
    const int lane = tid & 31;
    const int wid = tid >> 5;
    const int pl = lane >> 4;                 // pair 0/1
    const int f = (wid << 4) | (lane & 15);   // 0..63
    const int nl0 = pl * 2, nl1 = pl * 2 + 1;
    long long n0 = nbase + nl0;
    long long n1 = nbase + nl1;
    if (n0 > (long long)N - 1) n0 = N - 1;
    if (n1 > (long long)N - 1) n1 = N - 1;

    // x/y rows from shared (skewed slabs -> conflict-free), packed over pair
    const float* sx0 = s_x + nl0 * SLABP + f * 9;
    const float* sx1 = s_x + nl1 * SLABP + f * 9;
    const float* sy0 = s_y + nl0 * SLABP + f * 9;
    const float* sy1 = s_y + nl1 * SLABP + f * 9;
    u64 xp[9], yp[9];
#pragma unroll
    for (int a = 0; a < 9; a++) {
        xp[a] = pk2(sx0[a], sx1[a]);
        yp[a] = pk2(sy0[a], sy1[a]);
    }

    // Bernstein basis, packed over the pair
    float r0 = r[n0], r1 = r[n1];
    float u0 = fminf(fmaxf(r0 * 0.2f, 0.0f), 1.0f);
    float u1 = fminf(fmaxf(r1 * 0.2f, 0.0f), 1.0f);
    u64 uu = pk2(u0, u1);
    u64 vv = pk2(1.0f - u0, 1.0f - u1);
    const float binom[KK] = {1.f, 15.f, 105.f, 455.f, 1365.f, 3003.f, 5005.f, 6435.f,
                             6435.f, 5005.f, 3003.f, 1365.f, 455.f, 105.f, 15.f, 1.f};
    u64 gp[KK];
    {
        u64 pu[KK], pv[KK];
        pu[0] = rep2(1.0f);
        pv[0] = rep2(1.0f);
#pragma unroll
        for (int k = 1; k < KK; k++) {
            pu[k] = mul2(pu[k - 1], uu);
            pv[k] = mul2(pv[k - 1], vv);
        }
#pragma unroll
        for (int k = 0; k < KK; k++)
            gp[k] = mul2(mul2(pu[k], pv[(KK - 1) - k]), rep2(binom[k]));
    }

    // main contraction
    const int bases[9] = {0, 10, 40, 90, 120, 210, 360, 410, 560};
    u64 outp[9];
#pragma unroll
    for (int c = 0; c < 9; c++) outp[c] = 0ull;

#pragma unroll
    for (int l1 = 0; l1 < 3; l1++) {
#pragma unroll
        for (int l2 = 0; l2 < 3; l2++) {
            const int d1 = 2 * l1 + 1;
            const int d2 = 2 * l2 + 1;
            const int idx0 = l1 * 9 + l2 * 3;
            const u64* cgblk = s_cg + bases[l1 * 3 + l2];

            // radial mix for the 3 l3's (float4 weight loads, lane-deduped)
            u64 ml[3];
#pragma unroll
            for (int l3 = 0; l3 < 3; l3++) {
                const float4* w = d_Wt4 + ((idx0 + l3) * 4) * NF + f;
                u64 a0 = 0ull, a1 = 0ull;
#pragma unroll
                for (int kq = 0; kq < 4; kq++) {
                    float4 wv = w[kq * NF];
                    a0 = fma2(rep2(wv.x), gp[4 * kq + 0], a0);
                    a1 = fma2(rep2(wv.y), gp[4 * kq + 1], a1);
                    a0 = fma2(rep2(wv.z), gp[4 * kq + 2], a0);
                    a1 = fma2(rep2(wv.w), gp[4 * kq + 3], a1);
                }
                ml[l3] = add2(a0, a1);
            }

            // U_c = sum_ab x_a y_b cg[abc]  (c innermost, 9 independent chains)
            u64 U[9];
#pragma unroll
            for (int c = 0; c < 9; c++) U[c] = 0ull;
#pragma unroll
            for (int a = 0; a < d1; a++) {
                const u64 xa = xp[l1 * l1 + a];
#pragma unroll
                for (int b = 0; b < d2; b++) {
                    const u64 p = mul2(xa, yp[l2 * l2 + b]);
                    const u64* row = cgblk + (a * d2 + b) * 10;
#pragma unroll
                    for (int cq = 0; cq < 4; cq++) {
                        ulonglong2 v = *(const ulonglong2*)(row + 2 * cq);
                        U[2 * cq]     = fma2(p, v.x, U[2 * cq]);
                        U[2 * cq + 1] = fma2(p, v.y, U[2 * cq + 1]);
                    }
                    U[8] = fma2(p, row[8], U[8]);   // last useful c (pad dropped)
                }
            }
            // epilogue: out_c += U_c * ml[l3(c)]
            outp[0] = fma2(U[0], ml[0], outp[0]);
#pragma unroll
            for (int c = 1; c < 4; c++) outp[c] = fma2(U[c], ml[1], outp[c]);
#pragma unroll
            for (int c = 4; c < 9; c++) outp[c] = fma2(U[c], ml[2], outp[c]);
        }
    }

    // store: stage into reused s_x (skewed), then dense float4 STG
    __syncthreads();
    {
        float* so0 = s_x + nl0 * SLABP + f * 9;
        float* so1 = s_x + nl1 * SLABP + f * 9;
#pragma unroll
        for (int c = 0; c < 9; c++) {
            float a, b;
            unpk2(outp[c], a, b);
            so0[c] = a;
            so1[c] = b;
        }
    }
    __syncthreads();
    {
        float4* go = (float4*)(out + nbase * SLABF);
        int tot4 = totf >> 2;
        for (int i = tid; i < tot4; i += TPB) {
            int si = i + (i / 144) * (SKEW / 4);
            go[i] = ((float4*)s_x)[si];
        }
    }
}

// ---------------------------------------------------------------------------
extern "C" void kernel_launch(void* const* d_in, const int* in_sizes, int n_in,
                              void* d_out, int out_size) {
    const float* x = (const float*)d_in[0];
    const float* y = (const float*)d_in[1];
    const float* r = (const float*)d_in[2];
    const float* weights = (const float*)d_in[3];
    const float* cgc = (const float*)d_in[4];
    float* out = (float*)d_out;

    int N = in_sizes[2];  // r has N elements

    int stot = WTOT + CG2TOT;
    setup_kernel<<<(stot + 255) / 256, 256>>>(weights, cgc);

    int blocks = (N + NPB - 1) / NPB;
    pairmix_kernel<<<blocks, TPB>>>(x, y, r, out, N);
}

// round 16
// speedup vs baseline: 2.4392x; 1.1849x over previous
#include <cuda_runtime.h>

// PairmixLayer: out[n,f,l3^2+c] = sum_{l1,l2} (sum_{a,b} x[n,f,l1^2+a] y[n,f,l2^2+b] cg[l1,l2,l3,a,b,c])
//                                 * (sum_k W[idx(l1,l2,l3)][f][k] g[n,k])
// N=150000, F=64, K=16, L=2.
// R16 = R15 resubmitted after infra failure:
// 2 n-pairs (4 n) per thread -> cg LDS + weight LDG amortized 2x;
// direct accumulation (no U[] intermediate); SKEW=4 slab padding keeps all
// 8 n-slabs on disjoint LDS bank sets; 8 n per block; launch_bounds(128,2).

#define NF   64
#define KK   16
#define NIDX 27
#define TPB  128
#define NPB  8                         // n per block
#define SLABF (NF * 9)                 // 576 floats per n
#define SLABP (SLABF + 4)              // 580: slab stride = 4 mod 32 banks
#define CG2TOT 810                     // u64 slots
#define WTOT  (NIDX * 4 * NF)          // 6912 float4 elems

typedef unsigned long long u64;

__device__ float4 d_Wt4[WTOT];   // [idx][kq][f] = W[idx][f][4kq..4kq+3]
__device__ u64 d_cgq2[CG2TOT];   // per (l1,l2): rows of 10 u64 per (a,b), c-innermost

__device__ __forceinline__ u64 pk2(float lo, float hi) {
    u64 r; asm("mov.b64 %0, {%1,%2};" : "=l"(r) : "f"(lo), "f"(hi)); return r;
}
__device__ __forceinline__ void unpk2(u64 v, float& a, float& b) {
    asm("mov.b64 {%0,%1}, %2;" : "=f"(a), "=f"(b) : "l"(v));
}
__device__ __forceinline__ u64 rep2(float x) {
    u64 r; asm("mov.b64 %0, {%1,%1};" : "=l"(r) : "f"(x)); return r;
}
__device__ __forceinline__ u64 fma2(u64 a, u64 b, u64 c) {
    u64 r; asm("fma.rn.f32x2 %0, %1, %2, %3;" : "=l"(r) : "l"(a), "l"(b), "l"(c)); return r;
}
__device__ __forceinline__ u64 mul2(u64 a, u64 b) {
    u64 r; asm("mul.rn.f32x2 %0, %1, %2;" : "=l"(r) : "l"(a), "l"(b)); return r;
}
__device__ __forceinline__ u64 add2(u64 a, u64 b) {
    u64 r; asm("add.rn.f32x2 %0, %1, %2;" : "=l"(r) : "l"(a), "l"(b)); return r;
}

// Bernstein basis (packed over an n-pair) from clamped u values.
__device__ __forceinline__ void bern16(float u0, float u1, u64* gp) {
    const float binom[KK] = {1.f, 15.f, 105.f, 455.f, 1365.f, 3003.f, 5005.f, 6435.f,
                             6435.f, 5005.f, 3003.f, 1365.f, 455.f, 105.f, 15.f, 1.f};
    u64 uu = pk2(u0, u1);
    u64 vv = pk2(1.0f - u0, 1.0f - u1);
    u64 pu[KK], pv[KK];
    pu[0] = rep2(1.0f);
    pv[0] = rep2(1.0f);
#pragma unroll
    for (int k = 1; k < KK; k++) {
        pu[k] = mul2(pu[k - 1], uu);
        pv[k] = mul2(pv[k - 1], vv);
    }
#pragma unroll
    for (int k = 0; k < KK; k++)
        gp[k] = mul2(mul2(pu[k], pv[(KK - 1) - k]), rep2(binom[k]));
}

// ---------------------------------------------------------------------------
// Merged setup kernel: weights repack + cg prepack in one launch.
// ---------------------------------------------------------------------------
__global__ void setup_kernel(const float* __restrict__ W,
                             const float* __restrict__ cgc) {
    int i = blockIdx.x * blockDim.x + threadIdx.x;
    if (i < WTOT) {
        int idx = i / (4 * NF);
        int rem = i % (4 * NF);
        int kq = rem / NF;
        int f = rem % NF;
        const float* src = W + (idx * NF + f) * KK + 4 * kq;
        d_Wt4[i] = make_float4(src[0], src[1], src[2], src[3]);
    } else {
        int j = i - WTOT;
        if (j < CG2TOT) {
            const int bases[10] = {0, 10, 40, 90, 120, 210, 360, 410, 560, 810};
            int g = 0;
            while (j >= bases[g + 1]) g++;
            int l1 = g / 3, l2 = g % 3;
            int off = j - bases[g];
            int ab = off / 10, c = off % 10;
            int d2 = 2 * l2 + 1;
            int a = ab / d2, b = ab % d2;
            u64 v = 0ull;
            if (c < 9) {
                int l3 = (c >= 4) ? 2 : (c >= 1 ? 1 : 0);
                int cl = c - l3 * l3;
                int idx = l1 * 9 + l2 * 3 + l3;
                v = rep2(cgc[idx * 125 + a * 25 + b * 5 + cl]);
            }
            d_cgq2[j] = v;
        }
    }
}

// ---------------------------------------------------------------------------
// Main kernel. 128 threads, 8 n per block, thread = (f, 2 n-pairs).
// Warp: lanes 0-15 -> pairs {0,1}, lanes 16-31 -> pairs {2,3}, same f set
// (weight LDG dedup across half-warps preserved).
// ---------------------------------------------------------------------------
__global__ __launch_bounds__(TPB, 2)
void pairmix_kernel(const float* __restrict__ x,
                    const float* __restrict__ y,
                    const float* __restrict__ r,
                    float* __restrict__ out,
                    int N) {
    __shared__ __align__(16) u64 s_cg[CG2TOT];          //  6480 B
    __shared__ __align__(16) float s_x[NPB * SLABP];    // 18560 B (reused for out)
    __shared__ __align__(16) float s_y[NPB * SLABP];    // 18560 B

    const int tid = threadIdx.x;
    const long long nbase = (long long)blockIdx.x * NPB;
    int cnt = N - (int)nbase;
    if (cnt > NPB) cnt = NPB;
    const int totf = cnt * SLABF;

    // copy prepacked cg linearly (float4)
    {
        const float4* src = (const float4*)d_cgq2;
        float4* dst = (float4*)s_cg;
#pragma unroll
        for (int i = tid; i < CG2TOT >> 1; i += TPB) dst[i] = src[i];
    }
    // stage x, y dense (float4), skew of 1 float4 per n-slab
    {
        const float4* gx = (const float4*)(x + nbase * SLABF);
        const float4* gy = (const float4*)(y + nbase * SLABF);
        int tot4 = totf >> 2;                 // 144 float4 per n
        for (int i = tid; i < tot4; i += TPB) {
            int di = i + i / 144;
            ((float4*)s_x)[di] = gx[i];
            ((float4*)s_y)[di] = gy[i];
        }
    }
    __syncthreads();

    const int lane = tid & 31;
    const int wid = tid >> 5;
    const int f = (wid << 4) | (lane & 15);   // 0..63
    const int half = lane >> 4;               // 0/1
    const int s0 = half * 4;                  // this thread's first n-slab
    long long nn[4];
#pragma unroll
    for (int j = 0; j < 4; j++) {
        long long v = nbase + s0 + j;
        nn[j] = (v > (long long)N - 1) ? (long long)N - 1 : v;
    }

    // x/y rows from shared: pairs A=(s0,s0+1), B=(s0+2,s0+3)
    u64 xpA[9], ypA[9], xpB[9], ypB[9];
    {
        const float* a0 = s_x + (s0 + 0) * SLABP + f * 9;
        const float* a1 = s_x + (s0 + 1) * SLABP + f * 9;
        const float* b0 = s_x + (s0 + 2) * SLABP + f * 9;
        const float* b1 = s_x + (s0 + 3) * SLABP + f * 9;
        const float* c0 = s_y + (s0 + 0) * SLABP + f * 9;
        const float* c1 = s_y + (s0 + 1) * SLABP + f * 9;
        const float* e0 = s_y + (s0 + 2) * SLABP + f * 9;
        const float* e1 = s_y + (s0 + 3) * SLABP + f * 9;
#pragma unroll
        for (int a = 0; a < 9; a++) {
            xpA[a] = pk2(a0[a], a1[a]);
            xpB[a] = pk2(b0[a], b1[a]);
            ypA[a] = pk2(c0[a], c1[a]);
            ypB[a] = pk2(e0[a], e1[a]);
        }
    }

    // Bernstein bases for both pairs
    u64 gpA[KK], gpB[KK];
    {
        float rA0 = r[nn[0]], rA1 = r[nn[1]], rB0 = r[nn[2]], rB1 = r[nn[3]];
        float uA0 = fminf(fmaxf(rA0 * 0.2f, 0.0f), 1.0f);
        float uA1 = fminf(fmaxf(rA1 * 0.2f, 0.0f), 1.0f);
        float uB0 = fminf(fmaxf(rB0 * 0.2f, 0.0f), 1.0f);
        float uB1 = fminf(fmaxf(rB1 * 0.2f, 0.0f), 1.0f);
        bern16(uA0, uA1, gpA);
        bern16(uB0, uB1, gpB);
    }

    // main contraction, direct accumulation
    const int bases[9] = {0, 10, 40, 90, 120, 210, 360, 410, 560};
    u64 outA[9], outB[9];
#pragma unroll
    for (int c = 0; c < 9; c++) { outA[c] = 0ull; outB[c] = 0ull; }

#pragma unroll
    for (int l1 = 0; l1 < 3; l1++) {
#pragma unroll
        for (int l2 = 0; l2 < 3; l2++) {
            const int d1 = 2 * l1 + 1;
            const int d2 = 2 * l2 + 1;
            const int idx0 = l1 * 9 + l2 * 3;
            const u64* cgblk = s_cg + bases[l1 * 3 + l2];

            // radial mix for both pairs; weight float4 loaded once
            u64 mlA[3], mlB[3];
#pragma unroll
            for (int l3 = 0; l3 < 3; l3++) {
                const float4* w = d_Wt4 + ((idx0 + l3) * 4) * NF + f;
                u64 aA0 = 0ull, aA1 = 0ull, aB0 = 0ull, aB1 = 0ull;
#pragma unroll
                for (int kq = 0; kq < 4; kq++) {
                    float4 wv = w[kq * NF];
                    u64 wx = rep2(wv.x), wy = rep2(wv.y), wz = rep2(wv.z), ww = rep2(wv.w);
                    aA0 = fma2(wx, gpA[4 * kq + 0], aA0);
                    aA1 = fma2(wy, gpA[4 * kq + 1], aA1);
                    aA0 = fma2(wz, gpA[4 * kq + 2], aA0);
                    aA1 = fma2(ww, gpA[4 * kq + 3], aA1);
                    aB0 = fma2(wx, gpB[4 * kq + 0], aB0);
                    aB1 = fma2(wy, gpB[4 * kq + 1], aB1);
                    aB0 = fma2(wz, gpB[4 * kq + 2], aB0);
                    aB1 = fma2(ww, gpB[4 * kq + 3], aB1);
                }
                mlA[l3] = add2(aA0, aA1);
                mlB[l3] = add2(aB0, aB1);
            }

            // out_c += (x_a y_b ml[l3(c)]) * cg[abc]; cg shared by both pairs
#pragma unroll
            for (int a = 0; a < d1; a++) {
                const u64 xaA = xpA[l1 * l1 + a];
                const u64 xaB = xpB[l1 * l1 + a];
#pragma unroll
                for (int b = 0; b < d2; b++) {
                    const u64 pA = mul2(xaA, ypA[l2 * l2 + b]);
                    const u64 pB = mul2(xaB, ypB[l2 * l2 + b]);
                    const u64* row = cgblk + (a * d2 + b) * 10;
                    ulonglong2 v01 = *(const ulonglong2*)(row + 0);
                    ulonglong2 v23 = *(const ulonglong2*)(row + 2);
                    ulonglong2 v45 = *(const ulonglong2*)(row + 4);
                    ulonglong2 v67 = *(const ulonglong2*)(row + 6);
                    u64 v8 = row[8];

                    u64 pmA = mul2(pA, mlA[0]);
                    u64 pmB = mul2(pB, mlB[0]);
                    outA[0] = fma2(pmA, v01.x, outA[0]);
                    outB[0] = fma2(pmB, v01.x, outB[0]);

                    pmA = mul2(pA, mlA[1]);
                    pmB = mul2(pB, mlB[1]);
                    outA[1] = fma2(pmA, v01.y, outA[1]);
                    outB[1] = fma2(pmB, v01.y, outB[1]);
                    outA[2] = fma2(pmA, v23.x, outA[2]);
                    outB[2] = fma2(pmB, v23.x, outB[2]);
                    outA[3] = fma2(pmA, v23.y, outA[3]);
                    outB[3] = fma2(pmB, v23.y, outB[3]);

                    pmA = mul2(pA, mlA[2]);
                    pmB = mul2(pB, mlB[2]);
                    outA[4] = fma2(pmA, v45.x, outA[4]);
                    outB[4] = fma2(pmB, v45.x, outB[4]);
                    outA[5] = fma2(pmA, v45.y, outA[5]);
                    outB[5] = fma2(pmB, v45.y, outB[5]);
                    outA[6] = fma2(pmA, v67.x, outA[6]);
                    outB[6] = fma2(pmB, v67.x, outB[6]);
                    outA[7] = fma2(pmA, v67.y, outA[7]);
                    outB[7] = fma2(pmB, v67.y, outB[7]);
                    outA[8] = fma2(pmA, v8, outA[8]);
                    outB[8] = fma2(pmB, v8, outB[8]);
                }
            }
        }
    }

    // store: stage into reused s_x (skewed slabs), then dense float4 STG
    __syncthreads();
    {
        float* oA0 = s_x + (s0 + 0) * SLABP + f * 9;
        float* oA1 = s_x + (s0 + 1) * SLABP + f * 9;
        float* oB0 = s_x + (s0 + 2) * SLABP + f * 9;
        float* oB1 = s_x + (s0 + 3) * SLABP + f * 9;
#pragma unroll
        for (int c = 0; c < 9; c++) {
            float a, b;
            unpk2(outA[c], a, b);
            oA0[c] = a;
            oA1[c] = b;
            unpk2(outB[c], a, b);
            oB0[c] = a;
            oB1[c] = b;
        }
    }
    __syncthreads();
    {
        float4* go = (float4*)(out + nbase * SLABF);
        int tot4 = totf >> 2;
        for (int i = tid; i < tot4; i += TPB) {
            int si = i + i / 144;
            go[i] = ((float4*)s_x)[si];
        }
    }
}

// ---------------------------------------------------------------------------
extern "C" void kernel_launch(void* const* d_in, const int* in_sizes, int n_in,
                              void* d_out, int out_size) {
    const float* x = (const float*)d_in[0];
    const float* y = (const float*)d_in[1];
    const float* r = (const float*)d_in[2];
    const float* weights = (const float*)d_in[3];
    const float* cgc = (const float*)d_in[4];
    float* out = (float*)d_out;

    int N = in_sizes[2];  // r has N elements

    int stot = WTOT + CG2TOT;
    setup_kernel<<<(stot + 255) / 256, 256>>>(weights, cgc);

    int blocks = (N + NPB - 1) / NPB;
    pairmix_kernel<<<blocks, TPB>>>(x, y, r, out, N);
}

// round 17
// speedup vs baseline: 2.5839x; 1.0593x over previous
#include <cuda_runtime.h>

// PairmixLayer: out[n,f,l3^2+c] = sum_{l1,l2} (sum_{a,b} x[n,f,l1^2+a] y[n,f,l2^2+b] cg[l1,l2,l3,a,b,c])
//                                 * (sum_k W[idx(l1,l2,l3)][f][k] g[n,k])
// N=150000, F=64, K=16, L=2.
// R17 = R16 + U-scheme accumulation (saves 324 FMA2/thread: no per-(a,b)
// ml muls; epilogue multiply instead) + per-l1/per-cell x/y reload from
// shared (frees ~50 regs to pay for U[9]x2). 4 n per thread, 8 n/block.

#define NF   64
#define KK   16
#define NIDX 27
#define TPB  128
#define NPB  8                         // n per block
#define SLABF (NF * 9)                 // 576 floats per n
#define SLABP (SLABF + 4)              // 580: slab stride = 4 mod 32 banks
#define CG2TOT 810                     // u64 slots
#define WTOT  (NIDX * 4 * NF)          // 6912 float4 elems

typedef unsigned long long u64;

__device__ float4 d_Wt4[WTOT];   // [idx][kq][f] = W[idx][f][4kq..4kq+3]
__device__ u64 d_cgq2[CG2TOT];   // per (l1,l2): rows of 10 u64 per (a,b), c-innermost

__device__ __forceinline__ u64 pk2(float lo, float hi) {
    u64 r; asm("mov.b64 %0, {%1,%2};" : "=l"(r) : "f"(lo), "f"(hi)); return r;
}
__device__ __forceinline__ void unpk2(u64 v, float& a, float& b) {
    asm("mov.b64 {%0,%1}, %2;" : "=f"(a), "=f"(b) : "l"(v));
}
__device__ __forceinline__ u64 rep2(float x) {
    u64 r; asm("mov.b64 %0, {%1,%1};" : "=l"(r) : "f"(x)); return r;
}
__device__ __forceinline__ u64 fma2(u64 a, u64 b, u64 c) {
    u64 r; asm("fma.rn.f32x2 %0, %1, %2, %3;" : "=l"(r) : "l"(a), "l"(b), "l"(c)); return r;
}
__device__ __forceinline__ u64 mul2(u64 a, u64 b) {
    u64 r; asm("mul.rn.f32x2 %0, %1, %2;" : "=l"(r) : "l"(a), "l"(b)); return r;
}
__device__ __forceinline__ u64 add2(u64 a, u64 b) {
    u64 r; asm("add.rn.f32x2 %0, %1, %2;" : "=l"(r) : "l"(a), "l"(b)); return r;
}

// Bernstein basis (packed over an n-pair) from clamped u values.
__device__ __forceinline__ void bern16(float u0, float u1, u64* gp) {
    const float binom[KK] = {1.f, 15.f, 105.f, 455.f, 1365.f, 3003.f, 5005.f, 6435.f,
                             6435.f, 5005.f, 3003.f, 1365.f, 455.f, 105.f, 15.f, 1.f};
    u64 uu = pk2(u0, u1);
    u64 vv = pk2(1.0f - u0, 1.0f - u1);
    u64 pu[KK], pv[KK];
    pu[0] = rep2(1.0f);
    pv[0] = rep2(1.0f);
#pragma unroll
    for (int k = 1; k < KK; k++) {
        pu[k] = mul2(pu[k - 1], uu);
        pv[k] = mul2(pv[k - 1], vv);
    }
#pragma unroll
    for (int k = 0; k < KK; k++)
        gp[k] = mul2(mul2(pu[k], pv[(KK - 1) - k]), rep2(binom[k]));
}

// ---------------------------------------------------------------------------
// Merged setup kernel: weights repack + cg prepack in one launch.
// ---------------------------------------------------------------------------
__global__ void setup_kernel(const float* __restrict__ W,
                             const float* __restrict__ cgc) {
    int i = blockIdx.x * blockDim.x + threadIdx.x;
    if (i < WTOT) {
        int idx = i / (4 * NF);
        int rem = i % (4 * NF);
        int kq = rem / NF;
        int f = rem % NF;
        const float* src = W + (idx * NF + f) * KK + 4 * kq;
        d_Wt4[i] = make_float4(src[0], src[1], src[2], src[3]);
    } else {
        int j = i - WTOT;
        if (j < CG2TOT) {
            const int bases[10] = {0, 10, 40, 90, 120, 210, 360, 410, 560, 810};
            int g = 0;
            while (j >= bases[g + 1]) g++;
            int l1 = g / 3, l2 = g % 3;
            int off = j - bases[g];
            int ab = off / 10, c = off % 10;
            int d2 = 2 * l2 + 1;
            int a = ab / d2, b = ab % d2;
            u64 v = 0ull;
            if (c < 9) {
                int l3 = (c >= 4) ? 2 : (c >= 1 ? 1 : 0);
                int cl = c - l3 * l3;
                int idx = l1 * 9 + l2 * 3 + l3;
                v = rep2(cgc[idx * 125 + a * 25 + b * 5 + cl]);
            }
            d_cgq2[j] = v;
        }
    }
}

// ---------------------------------------------------------------------------
// Main kernel. 128 threads, 8 n per block, thread = (f, 2 n-pairs).
// ---------------------------------------------------------------------------
__global__ __launch_bounds__(TPB, 2)
void pairmix_kernel(const float* __restrict__ x,
                    const float* __restrict__ y,
                    const float* __restrict__ r,
                    float* __restrict__ out,
                    int N) {
    __shared__ __align__(16) u64 s_cg[CG2TOT];          //  6480 B
    __shared__ __align__(16) float s_x[NPB * SLABP];    // 18560 B (reused for out)
    __shared__ __align__(16) float s_y[NPB * SLABP];    // 18560 B

    const int tid = threadIdx.x;
    const long long nbase = (long long)blockIdx.x * NPB;
    int cnt = N - (int)nbase;
    if (cnt > NPB) cnt = NPB;
    const int totf = cnt * SLABF;

    // copy prepacked cg linearly (float4)
    {
        const float4* src = (const float4*)d_cgq2;
        float4* dst = (float4*)s_cg;
#pragma unroll
        for (int i = tid; i < CG2TOT >> 1; i += TPB) dst[i] = src[i];
    }
    // stage x, y dense (float4), skew of 1 float4 per n-slab
    {
        const float4* gx = (const float4*)(x + nbase * SLABF);
        const float4* gy = (const float4*)(y + nbase * SLABF);
        int tot4 = totf >> 2;                 // 144 float4 per n
        for (int i = tid; i < tot4; i += TPB) {
            int di = i + i / 144;
            ((float4*)s_x)[di] = gx[i];
            ((float4*)s_y)[di] = gy[i];
        }
    }
    __syncthreads();

    const int lane = tid & 31;
    const int wid = tid >> 5;
    const int f = (wid << 4) | (lane & 15);   // 0..63
    const int half = lane >> 4;               // 0/1
    const int s0 = half * 4;                  // this thread's first n-slab
    long long nn[4];
#pragma unroll
    for (int j = 0; j < 4; j++) {
        long long v = nbase + s0 + j;
        nn[j] = (v > (long long)N - 1) ? (long long)N - 1 : v;
    }

    // base offsets into the 4 slabs for this thread's f
    const float* sx0 = s_x + (s0 + 0) * SLABP + f * 9;
    const float* sx1 = s_x + (s0 + 1) * SLABP + f * 9;
    const float* sx2 = s_x + (s0 + 2) * SLABP + f * 9;
    const float* sx3 = s_x + (s0 + 3) * SLABP + f * 9;
    const float* sy0 = s_y + (s0 + 0) * SLABP + f * 9;
    const float* sy1 = s_y + (s0 + 1) * SLABP + f * 9;
    const float* sy2 = s_y + (s0 + 2) * SLABP + f * 9;
    const float* sy3 = s_y + (s0 + 3) * SLABP + f * 9;

    // Bernstein bases for both pairs (gp lives in regs; x/y reloaded per cell)
    u64 gpA[KK], gpB[KK];
    {
        float rA0 = r[nn[0]], rA1 = r[nn[1]], rB0 = r[nn[2]], rB1 = r[nn[3]];
        bern16(fminf(fmaxf(rA0 * 0.2f, 0.0f), 1.0f),
               fminf(fmaxf(rA1 * 0.2f, 0.0f), 1.0f), gpA);
        bern16(fminf(fmaxf(rB0 * 0.2f, 0.0f), 1.0f),
               fminf(fmaxf(rB1 * 0.2f, 0.0f), 1.0f), gpB);
    }

    const int bases[9] = {0, 10, 40, 90, 120, 210, 360, 410, 560};
    u64 outA[9], outB[9];
#pragma unroll
    for (int c = 0; c < 9; c++) { outA[c] = 0ull; outB[c] = 0ull; }

#pragma unroll
    for (int l1 = 0; l1 < 3; l1++) {
        const int d1 = 2 * l1 + 1;
        // load x for this l1 (reused over 3 l2 cells)
        u64 xA[5], xB[5];
#pragma unroll
        for (int a = 0; a < d1; a++) {
            int o = l1 * l1 + a;
            xA[a] = pk2(sx0[o], sx1[o]);
            xB[a] = pk2(sx2[o], sx3[o]);
        }
#pragma unroll
        for (int l2 = 0; l2 < 3; l2++) {
            const int d2 = 2 * l2 + 1;
            const int idx0 = l1 * 9 + l2 * 3;
            const u64* cgblk = s_cg + bases[l1 * 3 + l2];

            // load y for this cell
            u64 yA[5], yB[5];
#pragma unroll
            for (int b = 0; b < d2; b++) {
                int o = l2 * l2 + b;
                yA[b] = pk2(sy0[o], sy1[o]);
                yB[b] = pk2(sy2[o], sy3[o]);
            }

            // radial mix for both pairs; weight float4 loaded once
            u64 mlA[3], mlB[3];
#pragma unroll
            for (int l3 = 0; l3 < 3; l3++) {
                const float4* w = d_Wt4 + ((idx0 + l3) * 4) * NF + f;
                u64 aA0 = 0ull, aA1 = 0ull, aB0 = 0ull, aB1 = 0ull;
#pragma unroll
                for (int kq = 0; kq < 4; kq++) {
                    float4 wv = w[kq * NF];
                    u64 wx = rep2(wv.x), wy = rep2(wv.y), wz = rep2(wv.z), ww = rep2(wv.w);
                    aA0 = fma2(wx, gpA[4 * kq + 0], aA0);
                    aA1 = fma2(wy, gpA[4 * kq + 1], aA1);
                    aA0 = fma2(wz, gpA[4 * kq + 2], aA0);
                    aA1 = fma2(ww, gpA[4 * kq + 3], aA1);
                    aB0 = fma2(wx, gpB[4 * kq + 0], aB0);
                    aB1 = fma2(wy, gpB[4 * kq + 1], aB1);
                    aB0 = fma2(wz, gpB[4 * kq + 2], aB0);
                    aB1 = fma2(ww, gpB[4 * kq + 3], aB1);
                }
                mlA[l3] = add2(aA0, aA1);
                mlB[l3] = add2(aB0, aB1);
            }

            // U_c = sum_ab p*cg[abc] (U-scheme; first iter uses mul, no init)
            u64 UA[9], UB[9];
#pragma unroll
            for (int a = 0; a < d1; a++) {
#pragma unroll
                for (int b = 0; b < d2; b++) {
                    const u64 pA = mul2(xA[a], yA[b]);
                    const u64 pB = mul2(xB[a], yB[b]);
                    const u64* row = cgblk + (a * d2 + b) * 10;
                    ulonglong2 v01 = *(const ulonglong2*)(row + 0);
                    ulonglong2 v23 = *(const ulonglong2*)(row + 2);
                    ulonglong2 v45 = *(const ulonglong2*)(row + 4);
                    ulonglong2 v67 = *(const ulonglong2*)(row + 6);
                    u64 v8 = row[8];
                    if (a == 0 && b == 0) {
                        UA[0] = mul2(pA, v01.x); UB[0] = mul2(pB, v01.x);
                        UA[1] = mul2(pA, v01.y); UB[1] = mul2(pB, v01.y);
                        UA[2] = mul2(pA, v23.x); UB[2] = mul2(pB, v23.x);
                        UA[3] = mul2(pA, v23.y); UB[3] = mul2(pB, v23.y);
                        UA[4] = mul2(pA, v45.x); UB[4] = mul2(pB, v45.x);
                        UA[5] = mul2(pA, v45.y); UB[5] = mul2(pB, v45.y);
                        UA[6] = mul2(pA, v67.x); UB[6] = mul2(pB, v67.x);
                        UA[7] = mul2(pA, v67.y); UB[7] = mul2(pB, v67.y);
                        UA[8] = mul2(pA, v8);    UB[8] = mul2(pB, v8);
                    } else {
                        UA[0] = fma2(pA, v01.x, UA[0]); UB[0] = fma2(pB, v01.x, UB[0]);
                        UA[1] = fma2(pA, v01.y, UA[1]); UB[1] = fma2(pB, v01.y, UB[1]);
                        UA[2] = fma2(pA, v23.x, UA[2]); UB[2] = fma2(pB, v23.x, UB[2]);
                        UA[3] = fma2(pA, v23.y, UA[3]); UB[3] = fma2(pB, v23.y, UB[3]);
                        UA[4] = fma2(pA, v45.x, UA[4]); UB[4] = fma2(pB, v45.x, UB[4]);
                        UA[5] = fma2(pA, v45.y, UA[5]); UB[5] = fma2(pB, v45.y, UB[5]);
                        UA[6] = fma2(pA, v67.x, UA[6]); UB[6] = fma2(pB, v67.x, UB[6]);
                        UA[7] = fma2(pA, v67.y, UA[7]); UB[7] = fma2(pB, v67.y, UB[7]);
                        UA[8] = fma2(pA, v8, UA[8]);    UB[8] = fma2(pB, v8, UB[8]);
                    }
                }
            }
            // epilogue: out_c += U_c * ml[l3(c)]
            outA[0] = fma2(UA[0], mlA[0], outA[0]);
            outB[0] = fma2(UB[0], mlB[0], outB[0]);
#pragma unroll
            for (int c = 1; c < 4; c++) {
                outA[c] = fma2(UA[c], mlA[1], outA[c]);
                outB[c] = fma2(UB[c], mlB[1], outB[c]);
            }
#pragma unroll
            for (int c = 4; c < 9; c++) {
                outA[c] = fma2(UA[c], mlA[2], outA[c]);
                outB[c] = fma2(UB[c], mlB[2], outB[c]);
            }
        }
    }

    // store: stage into reused s_x (skewed slabs), then dense float4 STG
    __syncthreads();
    {
        float* oA0 = s_x + (s0 + 0) * SLABP + f * 9;
        float* oA1 = s_x + (s0 + 1) * SLABP + f * 9;
        float* oB0 = s_x + (s0 + 2) * SLABP + f * 9;
        float* oB1 = s_x + (s0 + 3) * SLABP + f * 9;
#pragma unroll
        for (int c = 0; c < 9; c++) {
            float a, b;
            unpk2(outA[c], a, b);
            oA0[c] = a;
            oA1[c] = b;
            unpk2(outB[c], a, b);
            oB0[c] = a;
            oB1[c] = b;
        }
    }
    __syncthreads();
    {
        float4* go = (float4*)(out + nbase * SLABF);
        int tot4 = totf >> 2;
        for (int i = tid; i < tot4; i += TPB) {
            int si = i + i / 144;
            go[i] = ((float4*)s_x)[si];
        }
    }
}

// ---------------------------------------------------------------------------
extern "C" void kernel_launch(void* const* d_in, const int* in_sizes, int n_in,
                              void* d_out, int out_size) {
    const float* x = (const float*)d_in[0];
    const float* y = (const float*)d_in[1];
    const float* r = (const float*)d_in[2];
    const float* weights = (const float*)d_in[3];
    const float* cgc = (const float*)d_in[4];
    float* out = (float*)d_out;

    int N = in_sizes[2];  // r has N elements

    int stot = WTOT + CG2TOT;
    setup_kernel<<<(stot + 255) / 256, 256>>>(weights, cgc);

    int blocks = (N + NPB - 1) / NPB;
    pairmix_kernel<<<blocks, TPB>>>(x, y, r, out, N);
}